// round 12
// baseline (speedup 1.0000x reference)
#include <cuda_runtime.h>
#include <cuda_bf16.h>
#include <math.h>
#include <stdint.h>

#define NB 2
#define NN 8192
#define NC 128
#define NK 16
#define NP (NB*NN)
#define EPSF 1e-5f
#define SA 132
#define WSH 136              // packed-slab row stride in ushorts (128 + 8 pad)
#define SLAB (NC*WSH*2)      // slab bytes = 34816
#define KSPLIT 8
#define KCH (NN/KSPLIT)      // 1024 candidates per chunk
#define BCAP 20              // per-query append buffer capacity
#define BSTR 21              // buffer row stride (odd)

__device__ float g_t1[NP*NC];
__device__ float g_t2[NP*NC];
__device__ float g_vf[NP*NC];
__device__ float g_outpre[NP*NC];
__device__ int   g_idx[NP*NK];
__device__ float g_pd[NP*KSPLIT*NK];
__device__ int   g_pi[NP*KSPLIT*NK];

__device__ float g_Woutt[NC*NC];
__device__ float g_cc[NC];
__device__ float g_pW1s[NC*3];
__device__ float g_b1p[NC];

// bf16 hi/lo weight splits, [o][k] row-major ushorts
__device__ unsigned short g_Athi[NC*NC], g_Atlo[NC*NC];
__device__ unsigned short g_Bthi[NC*NC], g_Btlo[NC*NC];
__device__ unsigned short g_Wvhi[NC*NC], g_Wvlo[NC*NC];
__device__ unsigned short g_W3hi[NC*NC],  g_W3lo[NC*NC];
__device__ unsigned short g_pW2hi[NC*NC], g_pW2lo[NC*NC];
__device__ unsigned short g_aW2hi[NC*NC], g_aW2lo[NC*NC];

__device__ __forceinline__ void mma16(float* d, const unsigned* a, unsigned b0, unsigned b1) {
    asm volatile("mma.sync.aligned.m16n8k16.row.col.f32.bf16.bf16.f32 "
        "{%0,%1,%2,%3}, {%4,%5,%6,%7}, {%8,%9}, {%0,%1,%2,%3};"
        : "+f"(d[0]), "+f"(d[1]), "+f"(d[2]), "+f"(d[3])
        : "r"(a[0]), "r"(a[1]), "r"(a[2]), "r"(a[3]), "r"(b0), "r"(b1));
}

// split two fp32 into packed bf16x2 hi and lo words (x0 in low half)
__device__ __forceinline__ void split2(float x0, float x1, unsigned& hi, unsigned& lo) {
    __nv_bfloat16 h0 = __float2bfloat16_rn(x0), h1 = __float2bfloat16_rn(x1);
    float r0 = x0 - __bfloat162float(h0);
    float r1 = x1 - __bfloat162float(h1);
    __nv_bfloat16 l0 = __float2bfloat16_rn(r0), l1 = __float2bfloat16_rn(r1);
    hi = ((unsigned)__bfloat16_as_ushort(h1) << 16) | (unsigned)__bfloat16_as_ushort(h0);
    lo = ((unsigned)__bfloat16_as_ushort(l1) << 16) | (unsigned)__bfloat16_as_ushort(l0);
}
__device__ __forceinline__ void splitw(float x, unsigned short* hi, unsigned short* lo, int idx) {
    __nv_bfloat16 b = __float2bfloat16_rn(x);
    hi[idx] = __bfloat16_as_ushort(b);
    lo[idx] = __bfloat16_as_ushort(__float2bfloat16_rn(x - __bfloat162float(b)));
}

// ---------------- setup ----------------
__global__ void setup_kernel(
    const float* __restrict__ Wq, const float* __restrict__ Wk,
    const float* __restrict__ Wv, const float* __restrict__ pW1,
    const float* __restrict__ pb1, const float* __restrict__ pg,
    const float* __restrict__ pbeta, const float* __restrict__ pmean,
    const float* __restrict__ pvar, const float* __restrict__ pW2,
    const float* __restrict__ pb2, const float* __restrict__ aW1,
    const float* __restrict__ ab1, const float* __restrict__ ag,
    const float* __restrict__ abeta, const float* __restrict__ amean,
    const float* __restrict__ avar, const float* __restrict__ aW2,
    const float* __restrict__ Wout)
{
    __shared__ float arow[NC];
    int o = blockIdx.x, i = threadIdx.x;
    arow[i] = aW1[o*NC + i];
    __syncthreads();
    float s2o = ag[o] * rsqrtf(avar[o] + EPSF);
    float sA = 0.f, sB = 0.f, sW = 0.f;
    #pragma unroll 4
    for (int m = 0; m < NC; ++m) {
        float a = arow[m];
        sA = fmaf(a, Wq[m*NC + i], sA);
        sB = fmaf(a, Wk[m*NC + i], sB);
        sW = fmaf(a, pW2[m*NC + i], sW);
    }
    g_Woutt[i*NC + o] = Wout[o*NC + i];

    int e = o*NC + i;
    splitw(s2o * sA, g_Athi, g_Atlo, e);
    splitw(s2o * sB, g_Bthi, g_Btlo, e);
    splitw(Wv[e],    g_Wvhi, g_Wvlo, e);
    splitw(s2o * sW, g_W3hi, g_W3lo, e);
    splitw(pW2[e],   g_pW2hi, g_pW2lo, e);
    splitw(aW2[e],   g_aW2hi, g_aW2lo, e);

    if (o == 0) {
        int c = i;
        float s1 = pg[c] * rsqrtf(pvar[c] + EPSF);
        g_pW1s[c*3+0] = pW1[c*3+0] * s1;
        g_pW1s[c*3+1] = pW1[c*3+1] * s1;
        g_pW1s[c*3+2] = pW1[c*3+2] * s1;
        g_b1p[c] = (pb1[c] - pmean[c]) * s1 + pbeta[c];
        float s2c = ag[c] * rsqrtf(avar[c] + EPSF);
        float c0 = ab1[c];
        for (int m = 0; m < NC; ++m) c0 = fmaf(aW1[c*NC + m], pb2[m], c0);
        g_cc[c] = s2c * c0 + abeta[c] - amean[c] * s2c;
    }
}

// ---------------- top-16 insert (strict <; ascending visit order = top_k ties) ----------------
__device__ __forceinline__ void ins16(float d, int m, float bd[NK], int bi[NK]) {
    if (d < bd[NK-1]) {
        bd[NK-1] = d; bi[NK-1] = m;
        #pragma unroll
        for (int s = NK-1; s >= 1; --s) {
            if (bd[s] < bd[s-1]) {
                float td = bd[s]; bd[s] = bd[s-1]; bd[s-1] = td;
                int   ti = bi[s]; bi[s] = bi[s-1]; bi[s-1] = ti;
            }
        }
    }
}

// drain the append buffer through exact ins16 (append order = ascending index)
__device__ __forceinline__ void flushq(float* bD, int* bI, int& cnt, float bd[NK], int bi[NK]) {
    for (int k = 0; k < cnt; ++k) ins16(bD[k], bI[k], bd, bi);
    cnt = 0;
}
// append (stale-threshold superset); overflow flushes first so order is preserved
__device__ __forceinline__ void appq(float d, int m, float* bD, int* bI, int& cnt,
                                     float bd[NK], int bi[NK]) {
    if (d < bd[NK-1]) {
        if (cnt == BCAP) flushq(bD, bI, cnt, bd, bi);
        bD[cnt] = d; bI[cnt] = m; ++cnt;
    }
}

// ---------------- KNN stage 1: scalar distances + deferred coherent inserts ----------------
__global__ __launch_bounds__(128) void knn_part(
    const float* __restrict__ xyz, float* __restrict__ pd, int* __restrict__ pi)
{
    __shared__ float4 cand[256];
    __shared__ float bufD[256*BSTR];
    __shared__ int   bufI[256*BSTR];

    int tid = threadIdx.x;
    int qA = blockIdx.x * 256 + tid;
    int qB = qA + 128;
    int base = (qA / NN) * NN;
    int c0 = base + blockIdx.y * KCH;

    float nax = -2.f*xyz[(size_t)qA*3+0], nay = -2.f*xyz[(size_t)qA*3+1], naz = -2.f*xyz[(size_t)qA*3+2];
    float nbx = -2.f*xyz[(size_t)qB*3+0], nby = -2.f*xyz[(size_t)qB*3+1], nbz = -2.f*xyz[(size_t)qB*3+2];

    float* bDA = bufD + (2*tid)*BSTR;   int* bIA = bufI + (2*tid)*BSTR;
    float* bDB = bufD + (2*tid+1)*BSTR; int* bIB = bufI + (2*tid+1)*BSTR;
    int cA = 0, cB = 0;

    float bdA[NK], bdB[NK]; int biA[NK], biB[NK];
    #pragma unroll
    for (int k = 0; k < NK; ++k) {
        bdA[k] = INFINITY; biA[k] = 0;
        bdB[k] = INFINITY; biB[k] = 0;
    }

    for (int t0 = 0; t0 < KCH; t0 += 256) {
        __syncthreads();
        #pragma unroll
        for (int j = tid; j < 256; j += 128) {
            int m = c0 + t0 + j;
            float x = xyz[(size_t)m*3+0], y = xyz[(size_t)m*3+1], z = xyz[(size_t)m*3+2];
            cand[j] = make_float4(x, y, z, fmaf(x, x, fmaf(y, y, z*z)));
        }
        __syncthreads();

        #pragma unroll 1
        for (int hf = 0; hf < 2; ++hf) {
            int j0 = hf * 128;
            #pragma unroll 2
            for (int j = j0; j < j0 + 128; j += 4) {
                float4 q0 = cand[j], q1 = cand[j+1], q2 = cand[j+2], q3 = cand[j+3];
                float d0 = fmaf(nax,q0.x,fmaf(nay,q0.y,fmaf(naz,q0.z,q0.w)));
                float d1 = fmaf(nax,q1.x,fmaf(nay,q1.y,fmaf(naz,q1.z,q1.w)));
                float d2 = fmaf(nax,q2.x,fmaf(nay,q2.y,fmaf(naz,q2.z,q2.w)));
                float d3 = fmaf(nax,q3.x,fmaf(nay,q3.y,fmaf(naz,q3.z,q3.w)));
                if (fminf(fminf(d0,d1), fminf(d2,d3)) < bdA[NK-1]) {
                    appq(d0, t0+j,   bDA, bIA, cA, bdA, biA);
                    appq(d1, t0+j+1, bDA, bIA, cA, bdA, biA);
                    appq(d2, t0+j+2, bDA, bIA, cA, bdA, biA);
                    appq(d3, t0+j+3, bDA, bIA, cA, bdA, biA);
                }
                d0 = fmaf(nbx,q0.x,fmaf(nby,q0.y,fmaf(nbz,q0.z,q0.w)));
                d1 = fmaf(nbx,q1.x,fmaf(nby,q1.y,fmaf(nbz,q1.z,q1.w)));
                d2 = fmaf(nbx,q2.x,fmaf(nby,q2.y,fmaf(nbz,q2.z,q2.w)));
                d3 = fmaf(nbx,q3.x,fmaf(nby,q3.y,fmaf(nbz,q3.z,q3.w)));
                if (fminf(fminf(d0,d1), fminf(d2,d3)) < bdB[NK-1]) {
                    appq(d0, t0+j,   bDB, bIB, cB, bdB, biB);
                    appq(d1, t0+j+1, bDB, bIB, cB, bdB, biB);
                    appq(d2, t0+j+2, bDB, bIB, cB, bdB, biB);
                    appq(d3, t0+j+3, bDB, bIB, cB, bdB, biB);
                }
            }
            // coherent flush point: all lanes drain together
            flushq(bDA, bIA, cA, bdA, biA);
            flushq(bDB, bIB, cB, bdB, biB);
        }
    }

    size_t oA = (size_t)qA*(KSPLIT*NK) + blockIdx.y*NK;
    size_t oB = (size_t)qB*(KSPLIT*NK) + blockIdx.y*NK;
    #pragma unroll
    for (int k = 0; k < NK; ++k) {
        pd[oA+k] = bdA[k]; pi[oA+k] = c0 + biA[k];
        pd[oB+k] = bdB[k]; pi[oB+k] = c0 + biB[k];
    }
}

// ---------------- KNN stage 2: merge (round-6) ----------------
__global__ __launch_bounds__(128) void knn_merge(
    const float* __restrict__ pd, const int* __restrict__ pi, int* __restrict__ idxo)
{
    int q = blockIdx.x * 128 + threadIdx.x;
    float bd[NK]; int bi[NK];
    #pragma unroll
    for (int k = 0; k < NK; ++k) { bd[k] = INFINITY; bi[k] = 0x7fffffff; }
    size_t ib = (size_t)q * (KSPLIT*NK);
    for (int j = 0; j < KSPLIT*NK; ++j) {
        float d = pd[ib + j];
        int   m = pi[ib + j];
        if (d < bd[NK-1] || (d == bd[NK-1] && m < bi[NK-1])) {
            bd[NK-1] = d; bi[NK-1] = m;
            #pragma unroll
            for (int s = NK-1; s >= 1; --s) {
                bool sw = (bd[s] < bd[s-1]) || (bd[s] == bd[s-1] && bi[s] < bi[s-1]);
                if (sw) {
                    float td = bd[s]; bd[s] = bd[s-1]; bd[s-1] = td;
                    int   ti = bi[s]; bi[s] = bi[s-1]; bi[s-1] = ti;
                }
            }
        }
    }
    #pragma unroll
    for (int k = 0; k < NK; ++k) idxo[(size_t)q*NK + k] = bi[k];
}

// ---------------- stage a 128x128 ushort weight matrix into a smem slab ----------------
__device__ __forceinline__ void stage_w(const unsigned short* __restrict__ g,
                                        unsigned short* s, int tid)
{
    int row = tid >> 2, q = tid & 3;
    #pragma unroll
    for (int j = 0; j < 4; ++j)
        *(uint4*)(s + row*WSH + q*32 + j*8) = *(const uint4*)(g + row*NC + q*32 + j*8);
}

// ---------------- gemm3_tc: t1/t2/vf via bf16x3 tensor cores ----------------
__global__ __launch_bounds__(512, 1) void gemm3_tc(
    const float* __restrict__ feat, float* __restrict__ t1,
    float* __restrict__ t2, float* __restrict__ vf)
{
    extern __shared__ char smc[];
    unsigned short* AH  = (unsigned short*)(smc);
    unsigned short* AL  = (unsigned short*)(smc + SLAB);
    unsigned short* W0H = (unsigned short*)(smc + 2*SLAB);
    unsigned short* W0L = (unsigned short*)(smc + 3*SLAB);
    unsigned short* W1H = (unsigned short*)(smc + 4*SLAB);
    unsigned short* W1L = (unsigned short*)(smc + 5*SLAB);

    int tid = threadIdx.x;
    int lane = tid & 31, wid = tid >> 5;
    int gid = lane >> 2, tig = lane & 3;
    int wm = wid & 3, wn = wid >> 2;
    int p0 = blockIdx.x * 128;

    {
        int row = tid >> 2, q = tid & 3;
        const float* src = feat + (size_t)(p0 + row)*NC + q*32;
        #pragma unroll
        for (int j = 0; j < 32; j += 2) {
            float2 v = *(const float2*)(src + j);
            unsigned hi, lo;
            split2(v.x, v.y, hi, lo);
            *(unsigned*)(AH + row*WSH + q*32 + j) = hi;
            *(unsigned*)(AL + row*WSH + q*32 + j) = lo;
        }
    }
    stage_w(g_Athi, W0H, tid);
    stage_w(g_Atlo, W0L, tid);
    stage_w(g_Bthi, W1H, tid);
    stage_w(g_Btlo, W1L, tid);
    __syncthreads();

    float acc1[2][4][4], acc2[2][4][4];
    #pragma unroll
    for (int mt = 0; mt < 2; ++mt)
        #pragma unroll
        for (int nt = 0; nt < 4; ++nt)
            #pragma unroll
            for (int j = 0; j < 4; ++j) { acc1[mt][nt][j] = 0.f; acc2[mt][nt][j] = 0.f; }

    #pragma unroll
    for (int kc = 0; kc < 8; ++kc) {
        unsigned ah[2][4], al[2][4];
        #pragma unroll
        for (int mt = 0; mt < 2; ++mt) {
            int r = wm*32 + mt*16 + gid;
            int ao = r*WSH + kc*16 + 2*tig;
            ah[mt][0] = *(const unsigned*)(AH + ao);
            ah[mt][1] = *(const unsigned*)(AH + ao + 8*WSH);
            ah[mt][2] = *(const unsigned*)(AH + ao + 8);
            ah[mt][3] = *(const unsigned*)(AH + ao + 8*WSH + 8);
            al[mt][0] = *(const unsigned*)(AL + ao);
            al[mt][1] = *(const unsigned*)(AL + ao + 8*WSH);
            al[mt][2] = *(const unsigned*)(AL + ao + 8);
            al[mt][3] = *(const unsigned*)(AL + ao + 8*WSH + 8);
        }
        #pragma unroll
        for (int nt = 0; nt < 4; ++nt) {
            int o = wn*32 + nt*8 + gid;
            int bo = o*WSH + kc*16 + 2*tig;
            unsigned a_h0 = *(const unsigned*)(W0H + bo);
            unsigned a_h1 = *(const unsigned*)(W0H + bo + 8);
            unsigned a_l0 = *(const unsigned*)(W0L + bo);
            unsigned a_l1 = *(const unsigned*)(W0L + bo + 8);
            unsigned b_h0 = *(const unsigned*)(W1H + bo);
            unsigned b_h1 = *(const unsigned*)(W1H + bo + 8);
            unsigned b_l0 = *(const unsigned*)(W1L + bo);
            unsigned b_l1 = *(const unsigned*)(W1L + bo + 8);
            #pragma unroll
            for (int mt = 0; mt < 2; ++mt) {
                mma16(acc1[mt][nt], ah[mt], a_h0, a_h1);
                mma16(acc1[mt][nt], ah[mt], a_l0, a_l1);
                mma16(acc1[mt][nt], al[mt], a_h0, a_h1);
                mma16(acc2[mt][nt], ah[mt], b_h0, b_h1);
                mma16(acc2[mt][nt], ah[mt], b_l0, b_l1);
                mma16(acc2[mt][nt], al[mt], b_h0, b_h1);
            }
        }
    }

    #pragma unroll
    for (int mt = 0; mt < 2; ++mt) {
        int rL = p0 + wm*32 + mt*16 + gid;
        #pragma unroll
        for (int nt = 0; nt < 4; ++nt) {
            int c = wn*32 + nt*8 + 2*tig;
            *(float2*)(t1 + (size_t)rL*NC + c)     = make_float2(acc1[mt][nt][0], acc1[mt][nt][1]);
            *(float2*)(t1 + (size_t)(rL+8)*NC + c) = make_float2(acc1[mt][nt][2], acc1[mt][nt][3]);
            *(float2*)(t2 + (size_t)rL*NC + c)     = make_float2(acc2[mt][nt][0], acc2[mt][nt][1]);
            *(float2*)(t2 + (size_t)(rL+8)*NC + c) = make_float2(acc2[mt][nt][2], acc2[mt][nt][3]);
        }
    }

    __syncthreads();
    stage_w(g_Wvhi, W0H, tid);
    stage_w(g_Wvlo, W0L, tid);
    __syncthreads();

    #pragma unroll
    for (int mt = 0; mt < 2; ++mt)
        #pragma unroll
        for (int nt = 0; nt < 4; ++nt)
            #pragma unroll
            for (int j = 0; j < 4; ++j) acc1[mt][nt][j] = 0.f;

    #pragma unroll
    for (int kc = 0; kc < 8; ++kc) {
        unsigned ah[2][4], al[2][4];
        #pragma unroll
        for (int mt = 0; mt < 2; ++mt) {
            int r = wm*32 + mt*16 + gid;
            int ao = r*WSH + kc*16 + 2*tig;
            ah[mt][0] = *(const unsigned*)(AH + ao);
            ah[mt][1] = *(const unsigned*)(AH + ao + 8*WSH);
            ah[mt][2] = *(const unsigned*)(AH + ao + 8);
            ah[mt][3] = *(const unsigned*)(AH + ao + 8*WSH + 8);
            al[mt][0] = *(const unsigned*)(AL + ao);
            al[mt][1] = *(const unsigned*)(AL + ao + 8*WSH);
            al[mt][2] = *(const unsigned*)(AL + ao + 8);
            al[mt][3] = *(const unsigned*)(AL + ao + 8*WSH + 8);
        }
        #pragma unroll
        for (int nt = 0; nt < 4; ++nt) {
            int o = wn*32 + nt*8 + gid;
            int bo = o*WSH + kc*16 + 2*tig;
            unsigned bh0 = *(const unsigned*)(W0H + bo);
            unsigned bh1 = *(const unsigned*)(W0H + bo + 8);
            unsigned bl0 = *(const unsigned*)(W0L + bo);
            unsigned bl1 = *(const unsigned*)(W0L + bo + 8);
            #pragma unroll
            for (int mt = 0; mt < 2; ++mt) {
                mma16(acc1[mt][nt], ah[mt], bh0, bh1);
                mma16(acc1[mt][nt], ah[mt], bl0, bl1);
                mma16(acc1[mt][nt], al[mt], bh0, bh1);
            }
        }
    }
    #pragma unroll
    for (int mt = 0; mt < 2; ++mt) {
        int rL = p0 + wm*32 + mt*16 + gid;
        #pragma unroll
        for (int nt = 0; nt < 4; ++nt) {
            int c = wn*32 + nt*8 + 2*tig;
            *(float2*)(vf + (size_t)rL*NC + c)     = make_float2(acc1[mt][nt][0], acc1[mt][nt][1]);
            *(float2*)(vf + (size_t)(rL+8)*NC + c) = make_float2(acc1[mt][nt][2], acc1[mt][nt][3]);
        }
    }
}

// ---------------- fused_main: bf16x3 m16n8k16 tensor cores (round-6 proven) ----------------
__global__ __launch_bounds__(512, 1) void fused_main(
    const float* __restrict__ xyz, const float* __restrict__ pb2,
    float* __restrict__ outpre)
{
    extern __shared__ char smc[];
    unsigned short* AH  = (unsigned short*)(smc);
    unsigned short* AL  = (unsigned short*)(smc + SLAB);
    unsigned short* W0H = (unsigned short*)(smc + 2*SLAB);
    unsigned short* W0L = (unsigned short*)(smc + 3*SLAB);
    unsigned short* W1H = (unsigned short*)(smc + 4*SLAB);
    unsigned short* W1L = (unsigned short*)(smc + 5*SLAB);
    int*   nid = (int*)(smc + 6*SLAB);
    float* rel = (float*)(smc + 6*SLAB + 512);

    int tid = threadIdx.x;
    int lane = tid & 31, wid = tid >> 5;
    int gid = lane >> 2, tig = lane & 3;
    int wm = wid & 3, wn = wid >> 2;
    int p0 = blockIdx.x * 8;

    if (tid < 128) {
        int r = tid;
        int p = p0 + (r >> 4);
        int g = g_idx[(size_t)p*NK + (r & 15)];
        nid[r] = g;
        rel[r*3+0] = xyz[(size_t)g*3+0] - xyz[(size_t)p*3+0];
        rel[r*3+1] = xyz[(size_t)g*3+1] - xyz[(size_t)p*3+1];
        rel[r*3+2] = xyz[(size_t)g*3+2] - xyz[(size_t)p*3+2];
    }
    __syncthreads();

    {   // u = relu(pW1'*rel + b1'), split to bf16 hi/lo slabs
        int c = tid & 127;
        int r0 = tid >> 7;
        float w0 = g_pW1s[c*3+0], w1 = g_pW1s[c*3+1], w2 = g_pW1s[c*3+2];
        float bb = g_b1p[c];
        #pragma unroll
        for (int r = r0; r < 128; r += 4) {
            float v = fmaf(w0, rel[r*3+0], fmaf(w1, rel[r*3+1], fmaf(w2, rel[r*3+2], bb)));
            v = fmaxf(v, 0.f);
            __nv_bfloat16 bh = __float2bfloat16_rn(v);
            AH[r*WSH + c] = __bfloat16_as_ushort(bh);
            AL[r*WSH + c] = __bfloat16_as_ushort(__float2bfloat16_rn(v - __bfloat162float(bh)));
        }
    }

    stage_w(g_W3hi,  W0H, tid);
    stage_w(g_W3lo,  W0L, tid);
    stage_w(g_pW2hi, W1H, tid);
    stage_w(g_pW2lo, W1L, tid);
    __syncthreads();

    float acc1[2][4][4], acc2[2][4][4];
    #pragma unroll
    for (int mt = 0; mt < 2; ++mt)
        #pragma unroll
        for (int nt = 0; nt < 4; ++nt)
            #pragma unroll
            for (int j = 0; j < 4; ++j) { acc1[mt][nt][j] = 0.f; acc2[mt][nt][j] = 0.f; }

    // fused GEMM1a (W3') + GEMM1b (pW2), shared A = u
    #pragma unroll
    for (int kc = 0; kc < 8; ++kc) {
        unsigned ah[2][4], al[2][4];
        #pragma unroll
        for (int mt = 0; mt < 2; ++mt) {
            int r = wm*32 + mt*16 + gid;
            int ao = r*WSH + kc*16 + 2*tig;
            ah[mt][0] = *(const unsigned*)(AH + ao);
            ah[mt][1] = *(const unsigned*)(AH + ao + 8*WSH);
            ah[mt][2] = *(const unsigned*)(AH + ao + 8);
            ah[mt][3] = *(const unsigned*)(AH + ao + 8*WSH + 8);
            al[mt][0] = *(const unsigned*)(AL + ao);
            al[mt][1] = *(const unsigned*)(AL + ao + 8*WSH);
            al[mt][2] = *(const unsigned*)(AL + ao + 8);
            al[mt][3] = *(const unsigned*)(AL + ao + 8*WSH + 8);
        }
        #pragma unroll
        for (int nt = 0; nt < 4; ++nt) {
            int o = wn*32 + nt*8 + gid;
            int bo = o*WSH + kc*16 + 2*tig;
            unsigned w3h0 = *(const unsigned*)(W0H + bo);
            unsigned w3h1 = *(const unsigned*)(W0H + bo + 8);
            unsigned w3l0 = *(const unsigned*)(W0L + bo);
            unsigned w3l1 = *(const unsigned*)(W0L + bo + 8);
            unsigned p2h0 = *(const unsigned*)(W1H + bo);
            unsigned p2h1 = *(const unsigned*)(W1H + bo + 8);
            unsigned p2l0 = *(const unsigned*)(W1L + bo);
            unsigned p2l1 = *(const unsigned*)(W1L + bo + 8);
            #pragma unroll
            for (int mt = 0; mt < 2; ++mt) {
                mma16(acc1[mt][nt], ah[mt], w3h0, w3h1);
                mma16(acc1[mt][nt], ah[mt], w3l0, w3l1);
                mma16(acc1[mt][nt], al[mt], w3h0, w3h1);
                mma16(acc2[mt][nt], ah[mt], p2h0, p2h1);
                mma16(acc2[mt][nt], ah[mt], p2l0, p2l1);
                mma16(acc2[mt][nt], al[mt], p2h0, p2h1);
            }
        }
    }
    __syncthreads();

    // epilogue 1: h = relu(acc1 + t1[p] - t2[g] + cc) -> AH/AL
    #pragma unroll
    for (int mt = 0; mt < 2; ++mt) {
        int rL = wm*32 + mt*16 + gid;
        int p = p0 + wm*2 + mt;
        int g0 = nid[rL], g1 = nid[rL+8];
        #pragma unroll
        for (int nt = 0; nt < 4; ++nt) {
            int c = wn*32 + nt*8 + 2*tig;
            float2 t1v = *(const float2*)(g_t1 + (size_t)p*NC + c);
            float2 ccv = *(const float2*)(g_cc + c);
            float2 t20 = *(const float2*)(g_t2 + (size_t)g0*NC + c);
            float2 t21 = *(const float2*)(g_t2 + (size_t)g1*NC + c);
            float h00 = fmaxf(acc1[mt][nt][0] + t1v.x - t20.x + ccv.x, 0.f);
            float h01 = fmaxf(acc1[mt][nt][1] + t1v.y - t20.y + ccv.y, 0.f);
            float h10 = fmaxf(acc1[mt][nt][2] + t1v.x - t21.x + ccv.x, 0.f);
            float h11 = fmaxf(acc1[mt][nt][3] + t1v.y - t21.y + ccv.y, 0.f);
            unsigned hi, lo;
            split2(h00, h01, hi, lo);
            *(unsigned*)(AH + rL*WSH + c) = hi;
            *(unsigned*)(AL + rL*WSH + c) = lo;
            split2(h10, h11, hi, lo);
            *(unsigned*)(AH + (rL+8)*WSH + c) = hi;
            *(unsigned*)(AL + (rL+8)*WSH + c) = lo;
        }
    }

    // epilogue 2: pvr = acc2 + pb2 + vf[g]
    float pvr[2][4][4];
    #pragma unroll
    for (int mt = 0; mt < 2; ++mt) {
        int rL = wm*32 + mt*16 + gid;
        int g0 = nid[rL], g1 = nid[rL+8];
        #pragma unroll
        for (int nt = 0; nt < 4; ++nt) {
            int c = wn*32 + nt*8 + 2*tig;
            float2 pbv = *(const float2*)(pb2 + c);
            float2 v0 = *(const float2*)(g_vf + (size_t)g0*NC + c);
            float2 v1 = *(const float2*)(g_vf + (size_t)g1*NC + c);
            pvr[mt][nt][0] = acc2[mt][nt][0] + pbv.x + v0.x;
            pvr[mt][nt][1] = acc2[mt][nt][1] + pbv.y + v0.y;
            pvr[mt][nt][2] = acc2[mt][nt][2] + pbv.x + v1.x;
            pvr[mt][nt][3] = acc2[mt][nt][3] + pbv.y + v1.y;
        }
    }

    stage_w(g_aW2hi, W0H, tid);
    stage_w(g_aW2lo, W0L, tid);
    __syncthreads();

    // GEMM2: logits = h @ aW2^T  (ab2 cancels in softmax)
    #pragma unroll
    for (int mt = 0; mt < 2; ++mt)
        #pragma unroll
        for (int nt = 0; nt < 4; ++nt)
            #pragma unroll
            for (int j = 0; j < 4; ++j) acc1[mt][nt][j] = 0.f;

    #pragma unroll
    for (int kc = 0; kc < 8; ++kc) {
        unsigned ah[2][4], al[2][4];
        #pragma unroll
        for (int mt = 0; mt < 2; ++mt) {
            int r = wm*32 + mt*16 + gid;
            int ao = r*WSH + kc*16 + 2*tig;
            ah[mt][0] = *(const unsigned*)(AH + ao);
            ah[mt][1] = *(const unsigned*)(AH + ao + 8*WSH);
            ah[mt][2] = *(const unsigned*)(AH + ao + 8);
            ah[mt][3] = *(const unsigned*)(AH + ao + 8*WSH + 8);
            al[mt][0] = *(const unsigned*)(AL + ao);
            al[mt][1] = *(const unsigned*)(AL + ao + 8*WSH);
            al[mt][2] = *(const unsigned*)(AL + ao + 8);
            al[mt][3] = *(const unsigned*)(AL + ao + 8*WSH + 8);
        }
        #pragma unroll
        for (int nt = 0; nt < 4; ++nt) {
            int o = wn*32 + nt*8 + gid;
            int bo = o*WSH + kc*16 + 2*tig;
            unsigned bh0 = *(const unsigned*)(W0H + bo);
            unsigned bh1 = *(const unsigned*)(W0H + bo + 8);
            unsigned bl0 = *(const unsigned*)(W0L + bo);
            unsigned bl1 = *(const unsigned*)(W0L + bo + 8);
            #pragma unroll
            for (int mt = 0; mt < 2; ++mt) {
                mma16(acc1[mt][nt], ah[mt], bh0, bh1);
                mma16(acc1[mt][nt], ah[mt], bl0, bl1);
                mma16(acc1[mt][nt], al[mt], bh0, bh1);
            }
        }
    }

    // softmax over K + weighted reduce, in registers
    #pragma unroll
    for (int mt = 0; mt < 2; ++mt) {
        int p = p0 + wm*2 + mt;
        #pragma unroll
        for (int nt = 0; nt < 4; ++nt) {
            #pragma unroll
            for (int j = 0; j < 2; ++j) {
                float x0 = acc1[mt][nt][j], x1 = acc1[mt][nt][2+j];
                float m = fmaxf(x0, x1);
                m = fmaxf(m, __shfl_xor_sync(0xffffffffu, m, 4));
                m = fmaxf(m, __shfl_xor_sync(0xffffffffu, m, 8));
                m = fmaxf(m, __shfl_xor_sync(0xffffffffu, m, 16));
                float e0 = __expf(x0 - m), e1 = __expf(x1 - m);
                float s = e0 + e1;
                float a = fmaf(e0, pvr[mt][nt][j], e1 * pvr[mt][nt][2+j]);
                s += __shfl_xor_sync(0xffffffffu, s, 4);
                a += __shfl_xor_sync(0xffffffffu, a, 4);
                s += __shfl_xor_sync(0xffffffffu, s, 8);
                a += __shfl_xor_sync(0xffffffffu, a, 8);
                s += __shfl_xor_sync(0xffffffffu, s, 16);
                a += __shfl_xor_sync(0xffffffffu, a, 16);
                if (gid == 0)
                    outpre[(size_t)p*NC + wn*32 + nt*8 + 2*tig + j] = a / s;
            }
        }
    }
}

// ---------------- final GEMM (Wout, scalar) ----------------
__global__ __launch_bounds__(256) void gemm_rt(
    const float* __restrict__ A, const float* __restrict__ Wt, float* __restrict__ out)
{
    extern __shared__ float sm[];
    float* AS  = sm;
    float* WTs = AS + NC*SA;

    int tid = threadIdx.x, tx = tid & 15, ty = tid >> 4;
    int p0 = blockIdx.x * 128;

    #pragma unroll
    for (int it = 0; it < 16; ++it) {
        int e = (it*256 + tid) * 4;
        int r = e >> 7, c = e & 127;
        *(float4*)(AS + r*SA + c) = *(const float4*)(A + (size_t)(p0 + r)*NC + c);
    }

    float acc[8][8];
    #pragma unroll
    for (int ir = 0; ir < 8; ++ir)
        #pragma unroll
        for (int io = 0; io < 8; ++io) acc[ir][io] = 0.f;

    #pragma unroll 1
    for (int k0 = 0; k0 < NC; k0 += 16) {
        __syncthreads();
        int e = tid * 8;
        *(float4*)(WTs + e)     = *(const float4*)(Wt + k0*NC + e);
        *(float4*)(WTs + e + 4) = *(const float4*)(Wt + k0*NC + e + 4);
        __syncthreads();
        #pragma unroll
        for (int kk = 0; kk < 16; ++kk) {
            float wf[8];
            ((float4*)wf)[0] = *(const float4*)(WTs + kk*NC + tx*8);
            ((float4*)wf)[1] = *(const float4*)(WTs + kk*NC + tx*8 + 4);
            float af[8];
            #pragma unroll
            for (int ir = 0; ir < 8; ++ir) af[ir] = AS[(ty*8 + ir)*SA + k0 + kk];
            #pragma unroll
            for (int ir = 0; ir < 8; ++ir)
                #pragma unroll
                for (int io = 0; io < 8; ++io)
                    acc[ir][io] = fmaf(af[ir], wf[io], acc[ir][io]);
        }
    }

    #pragma unroll
    for (int ir = 0; ir < 8; ++ir) {
        int r = p0 + ty*8 + ir;
        #pragma unroll
        for (int io4 = 0; io4 < 8; io4 += 4) {
            float4 v;
            v.x = acc[ir][io4+0]; v.y = acc[ir][io4+1];
            v.z = acc[ir][io4+2]; v.w = acc[ir][io4+3];
            *(float4*)(out + (size_t)r*NC + tx*8 + io4) = v;
        }
    }
}

// ---------------- launch ----------------
#define GEMM_SMEM  ((NC*SA + 16*NC) * 4)
#define G3_SMEM    (6*SLAB)
#define MAIN_SMEM  (6*SLAB + 512 + NC*3*4)

extern "C" void kernel_launch(void* const* d_in, const int* in_sizes, int n_in,
                              void* d_out, int out_size)
{
    const float* xyz   = (const float*)d_in[0];
    const float* feat  = (const float*)d_in[1];
    const float* Wq    = (const float*)d_in[2];
    const float* Wk    = (const float*)d_in[3];
    const float* Wv    = (const float*)d_in[4];
    const float* pW1   = (const float*)d_in[5];
    const float* pb1   = (const float*)d_in[6];
    const float* pg    = (const float*)d_in[7];
    const float* pbeta = (const float*)d_in[8];
    const float* pmean = (const float*)d_in[9];
    const float* pvar  = (const float*)d_in[10];
    const float* pW2   = (const float*)d_in[11];
    const float* pb2   = (const float*)d_in[12];
    const float* aW1   = (const float*)d_in[13];
    const float* ab1   = (const float*)d_in[14];
    const float* ag    = (const float*)d_in[15];
    const float* abeta = (const float*)d_in[16];
    const float* amean = (const float*)d_in[17];
    const float* avar  = (const float*)d_in[18];
    const float* aW2   = (const float*)d_in[19];
    const float* ab2   = (const float*)d_in[20];  (void)ab2;
    const float* Wout  = (const float*)d_in[21];
    float* out = (float*)d_out;

    void *p_t1, *p_t2, *p_vf, *p_outpre, *p_idx, *p_pd, *p_pi, *p_Woutt;
    cudaGetSymbolAddress(&p_t1, g_t1);
    cudaGetSymbolAddress(&p_t2, g_t2);
    cudaGetSymbolAddress(&p_vf, g_vf);
    cudaGetSymbolAddress(&p_outpre, g_outpre);
    cudaGetSymbolAddress(&p_idx, g_idx);
    cudaGetSymbolAddress(&p_pd, g_pd);
    cudaGetSymbolAddress(&p_pi, g_pi);
    cudaGetSymbolAddress(&p_Woutt, g_Woutt);

    cudaFuncSetAttribute(gemm_rt,    cudaFuncAttributeMaxDynamicSharedMemorySize, GEMM_SMEM);
    cudaFuncSetAttribute(gemm3_tc,   cudaFuncAttributeMaxDynamicSharedMemorySize, G3_SMEM);
    cudaFuncSetAttribute(fused_main, cudaFuncAttributeMaxDynamicSharedMemorySize, MAIN_SMEM);

    setup_kernel<<<NC, NC>>>(Wq, Wk, Wv, pW1, pb1, pg, pbeta, pmean, pvar,
                             pW2, pb2, aW1, ab1, ag, abeta, amean, avar, aW2, Wout);

    knn_part<<<dim3(NP/256, KSPLIT), 128>>>(xyz, (float*)p_pd, (int*)p_pi);
    knn_merge<<<NP/128, 128>>>((const float*)p_pd, (const int*)p_pi, (int*)p_idx);

    gemm3_tc<<<NP/128, 512, G3_SMEM>>>(feat, (float*)p_t1, (float*)p_t2, (float*)p_vf);

    fused_main<<<NP/8, 512, MAIN_SMEM>>>(xyz, pb2, (float*)p_outpre);

    gemm_rt<<<NP/128, 256, GEMM_SMEM>>>((const float*)p_outpre, (const float*)p_Woutt, out);
}

// round 13
// speedup vs baseline: 3.1013x; 3.1013x over previous
#include <cuda_runtime.h>
#include <cuda_bf16.h>
#include <math.h>
#include <stdint.h>

#define NB 2
#define NN 8192
#define NC 128
#define NK 16
#define NP (NB*NN)
#define EPSF 1e-5f
#define SA 132
#define WSH 136              // packed-slab row stride in ushorts (128 + 8 pad)
#define SLAB (NC*WSH*2)      // slab bytes = 34816
#define KSPLIT 4
#define KCH (NN/KSPLIT)      // 2048 candidates per chunk

__device__ float g_t1[NP*NC];
__device__ float g_t2[NP*NC];
__device__ float g_vf[NP*NC];
__device__ float g_outpre[NP*NC];
__device__ int   g_idx[NP*NK];
__device__ float g_pd[NP*KSPLIT*NK];
__device__ int   g_pi[NP*KSPLIT*NK];

__device__ float g_Woutt[NC*NC];
__device__ float g_cc[NC];
__device__ float g_pW1s[NC*3];
__device__ float g_b1p[NC];

// bf16 hi/lo weight splits, [o][k] row-major ushorts
__device__ unsigned short g_Athi[NC*NC], g_Atlo[NC*NC];
__device__ unsigned short g_Bthi[NC*NC], g_Btlo[NC*NC];
__device__ unsigned short g_Wvhi[NC*NC], g_Wvlo[NC*NC];
__device__ unsigned short g_W3hi[NC*NC],  g_W3lo[NC*NC];
__device__ unsigned short g_pW2hi[NC*NC], g_pW2lo[NC*NC];
__device__ unsigned short g_aW2hi[NC*NC], g_aW2lo[NC*NC];

__device__ __forceinline__ void mma16(float* d, const unsigned* a, unsigned b0, unsigned b1) {
    asm volatile("mma.sync.aligned.m16n8k16.row.col.f32.bf16.bf16.f32 "
        "{%0,%1,%2,%3}, {%4,%5,%6,%7}, {%8,%9}, {%0,%1,%2,%3};"
        : "+f"(d[0]), "+f"(d[1]), "+f"(d[2]), "+f"(d[3])
        : "r"(a[0]), "r"(a[1]), "r"(a[2]), "r"(a[3]), "r"(b0), "r"(b1));
}

// split two fp32 into packed bf16x2 hi and lo words (x0 in low half)
__device__ __forceinline__ void split2(float x0, float x1, unsigned& hi, unsigned& lo) {
    __nv_bfloat16 h0 = __float2bfloat16_rn(x0), h1 = __float2bfloat16_rn(x1);
    float r0 = x0 - __bfloat162float(h0);
    float r1 = x1 - __bfloat162float(h1);
    __nv_bfloat16 l0 = __float2bfloat16_rn(r0), l1 = __float2bfloat16_rn(r1);
    hi = ((unsigned)__bfloat16_as_ushort(h1) << 16) | (unsigned)__bfloat16_as_ushort(h0);
    lo = ((unsigned)__bfloat16_as_ushort(l1) << 16) | (unsigned)__bfloat16_as_ushort(l0);
}
__device__ __forceinline__ void splitw(float x, unsigned short* hi, unsigned short* lo, int idx) {
    __nv_bfloat16 b = __float2bfloat16_rn(x);
    hi[idx] = __bfloat16_as_ushort(b);
    lo[idx] = __bfloat16_as_ushort(__float2bfloat16_rn(x - __bfloat162float(b)));
}

// ---------------- setup ----------------
__global__ void setup_kernel(
    const float* __restrict__ Wq, const float* __restrict__ Wk,
    const float* __restrict__ Wv, const float* __restrict__ pW1,
    const float* __restrict__ pb1, const float* __restrict__ pg,
    const float* __restrict__ pbeta, const float* __restrict__ pmean,
    const float* __restrict__ pvar, const float* __restrict__ pW2,
    const float* __restrict__ pb2, const float* __restrict__ aW1,
    const float* __restrict__ ab1, const float* __restrict__ ag,
    const float* __restrict__ abeta, const float* __restrict__ amean,
    const float* __restrict__ avar, const float* __restrict__ aW2,
    const float* __restrict__ Wout)
{
    __shared__ float arow[NC];
    int o = blockIdx.x, i = threadIdx.x;
    arow[i] = aW1[o*NC + i];
    __syncthreads();
    float s2o = ag[o] * rsqrtf(avar[o] + EPSF);
    float sA = 0.f, sB = 0.f, sW = 0.f;
    #pragma unroll 4
    for (int m = 0; m < NC; ++m) {
        float a = arow[m];
        sA = fmaf(a, Wq[m*NC + i], sA);
        sB = fmaf(a, Wk[m*NC + i], sB);
        sW = fmaf(a, pW2[m*NC + i], sW);
    }
    g_Woutt[i*NC + o] = Wout[o*NC + i];

    int e = o*NC + i;
    splitw(s2o * sA, g_Athi, g_Atlo, e);
    splitw(s2o * sB, g_Bthi, g_Btlo, e);
    splitw(Wv[e],    g_Wvhi, g_Wvlo, e);
    splitw(s2o * sW, g_W3hi, g_W3lo, e);
    splitw(pW2[e],   g_pW2hi, g_pW2lo, e);
    splitw(aW2[e],   g_aW2hi, g_aW2lo, e);

    if (o == 0) {
        int c = i;
        float s1 = pg[c] * rsqrtf(pvar[c] + EPSF);
        g_pW1s[c*3+0] = pW1[c*3+0] * s1;
        g_pW1s[c*3+1] = pW1[c*3+1] * s1;
        g_pW1s[c*3+2] = pW1[c*3+2] * s1;
        g_b1p[c] = (pb1[c] - pmean[c]) * s1 + pbeta[c];
        float s2c = ag[c] * rsqrtf(avar[c] + EPSF);
        float c0 = ab1[c];
        for (int m = 0; m < NC; ++m) c0 = fmaf(aW1[c*NC + m], pb2[m], c0);
        g_cc[c] = s2c * c0 + abeta[c] - amean[c] * s2c;
    }
}

// ---------------- KNN stage 1 (round-6 scalar, KSPLIT=4) ----------------
__device__ __forceinline__ void ins16(float d, int m, float bd[NK], int bi[NK]) {
    if (d < bd[NK-1]) {
        bd[NK-1] = d; bi[NK-1] = m;
        #pragma unroll
        for (int s = NK-1; s >= 1; --s) {
            if (bd[s] < bd[s-1]) {
                float td = bd[s]; bd[s] = bd[s-1]; bd[s-1] = td;
                int   ti = bi[s]; bi[s] = bi[s-1]; bi[s-1] = ti;
            }
        }
    }
}

__global__ __launch_bounds__(128) void knn_part(
    const float* __restrict__ xyz, float* __restrict__ pd, int* __restrict__ pi)
{
    int qA = blockIdx.x * 256 + threadIdx.x;
    int qB = qA + 128;
    int base = (qA / NN) * NN;
    int c0 = base + blockIdx.y * KCH;

    float nax = -2.f*xyz[(size_t)qA*3+0], nay = -2.f*xyz[(size_t)qA*3+1], naz = -2.f*xyz[(size_t)qA*3+2];
    float nbx = -2.f*xyz[(size_t)qB*3+0], nby = -2.f*xyz[(size_t)qB*3+1], nbz = -2.f*xyz[(size_t)qB*3+2];

    __shared__ float4 cand[256];
    float bdA[NK], bdB[NK]; int biA[NK], biB[NK];
    #pragma unroll
    for (int k = 0; k < NK; ++k) {
        bdA[k] = INFINITY; biA[k] = 0;
        bdB[k] = INFINITY; biB[k] = 0;
    }

    for (int t0 = 0; t0 < KCH; t0 += 256) {
        __syncthreads();
        #pragma unroll
        for (int j = threadIdx.x; j < 256; j += 128) {
            int m = c0 + t0 + j;
            float x = xyz[(size_t)m*3+0], y = xyz[(size_t)m*3+1], z = xyz[(size_t)m*3+2];
            cand[j] = make_float4(x, y, z, fmaf(x, x, fmaf(y, y, z*z)));
        }
        __syncthreads();
        #pragma unroll 2
        for (int j = 0; j < 256; j += 4) {
            float4 q0 = cand[j], q1 = cand[j+1], q2 = cand[j+2], q3 = cand[j+3];
            float d0 = fmaf(nax,q0.x,fmaf(nay,q0.y,fmaf(naz,q0.z,q0.w)));
            float d1 = fmaf(nax,q1.x,fmaf(nay,q1.y,fmaf(naz,q1.z,q1.w)));
            float d2 = fmaf(nax,q2.x,fmaf(nay,q2.y,fmaf(naz,q2.z,q2.w)));
            float d3 = fmaf(nax,q3.x,fmaf(nay,q3.y,fmaf(naz,q3.z,q3.w)));
            if (fminf(fminf(d0,d1), fminf(d2,d3)) < bdA[NK-1]) {
                ins16(d0, t0+j, bdA, biA);   ins16(d1, t0+j+1, bdA, biA);
                ins16(d2, t0+j+2, bdA, biA); ins16(d3, t0+j+3, bdA, biA);
            }
            d0 = fmaf(nbx,q0.x,fmaf(nby,q0.y,fmaf(nbz,q0.z,q0.w)));
            d1 = fmaf(nbx,q1.x,fmaf(nby,q1.y,fmaf(nbz,q1.z,q1.w)));
            d2 = fmaf(nbx,q2.x,fmaf(nby,q2.y,fmaf(nbz,q2.z,q2.w)));
            d3 = fmaf(nbx,q3.x,fmaf(nby,q3.y,fmaf(nbz,q3.z,q3.w)));
            if (fminf(fminf(d0,d1), fminf(d2,d3)) < bdB[NK-1]) {
                ins16(d0, t0+j, bdB, biB);   ins16(d1, t0+j+1, bdB, biB);
                ins16(d2, t0+j+2, bdB, biB); ins16(d3, t0+j+3, bdB, biB);
            }
        }
    }
    size_t oA = (size_t)qA*(KSPLIT*NK) + blockIdx.y*NK;
    size_t oB = (size_t)qB*(KSPLIT*NK) + blockIdx.y*NK;
    #pragma unroll
    for (int k = 0; k < NK; ++k) {
        pd[oA+k] = bdA[k]; pi[oA+k] = c0 + biA[k];
        pd[oB+k] = bdB[k]; pi[oB+k] = c0 + biB[k];
    }
}

// ---------------- KNN stage 2: merge ----------------
__global__ __launch_bounds__(128) void knn_merge(
    const float* __restrict__ pd, const int* __restrict__ pi, int* __restrict__ idxo)
{
    int q = blockIdx.x * 128 + threadIdx.x;
    float bd[NK]; int bi[NK];
    #pragma unroll
    for (int k = 0; k < NK; ++k) { bd[k] = INFINITY; bi[k] = 0x7fffffff; }
    size_t ib = (size_t)q * (KSPLIT*NK);
    for (int j = 0; j < KSPLIT*NK; ++j) {
        float d = pd[ib + j];
        int   m = pi[ib + j];
        if (d < bd[NK-1] || (d == bd[NK-1] && m < bi[NK-1])) {
            bd[NK-1] = d; bi[NK-1] = m;
            #pragma unroll
            for (int s = NK-1; s >= 1; --s) {
                bool sw = (bd[s] < bd[s-1]) || (bd[s] == bd[s-1] && bi[s] < bi[s-1]);
                if (sw) {
                    float td = bd[s]; bd[s] = bd[s-1]; bd[s-1] = td;
                    int   ti = bi[s]; bi[s] = bi[s-1]; bi[s-1] = ti;
                }
            }
        }
    }
    #pragma unroll
    for (int k = 0; k < NK; ++k) idxo[(size_t)q*NK + k] = bi[k];
}

// ---------------- stage a 128x128 ushort weight matrix into a smem slab ----------------
__device__ __forceinline__ void stage_w(const unsigned short* __restrict__ g,
                                        unsigned short* s, int tid)
{
    int row = tid >> 2, q = tid & 3;
    #pragma unroll
    for (int j = 0; j < 4; ++j)
        *(uint4*)(s + row*WSH + q*32 + j*8) = *(const uint4*)(g + row*NC + q*32 + j*8);
}

// ---------------- gemm3_tc: t1/t2/vf via bf16x3 tensor cores ----------------
__global__ __launch_bounds__(512, 1) void gemm3_tc(
    const float* __restrict__ feat, float* __restrict__ t1,
    float* __restrict__ t2, float* __restrict__ vf)
{
    extern __shared__ char smc[];
    unsigned short* AH  = (unsigned short*)(smc);
    unsigned short* AL  = (unsigned short*)(smc + SLAB);
    unsigned short* W0H = (unsigned short*)(smc + 2*SLAB);
    unsigned short* W0L = (unsigned short*)(smc + 3*SLAB);
    unsigned short* W1H = (unsigned short*)(smc + 4*SLAB);
    unsigned short* W1L = (unsigned short*)(smc + 5*SLAB);

    int tid = threadIdx.x;
    int lane = tid & 31, wid = tid >> 5;
    int gid = lane >> 2, tig = lane & 3;
    int wm = wid & 3, wn = wid >> 2;
    int p0 = blockIdx.x * 128;

    {
        int row = tid >> 2, q = tid & 3;
        const float* src = feat + (size_t)(p0 + row)*NC + q*32;
        #pragma unroll
        for (int j = 0; j < 32; j += 2) {
            float2 v = *(const float2*)(src + j);
            unsigned hi, lo;
            split2(v.x, v.y, hi, lo);
            *(unsigned*)(AH + row*WSH + q*32 + j) = hi;
            *(unsigned*)(AL + row*WSH + q*32 + j) = lo;
        }
    }
    stage_w(g_Athi, W0H, tid);
    stage_w(g_Atlo, W0L, tid);
    stage_w(g_Bthi, W1H, tid);
    stage_w(g_Btlo, W1L, tid);
    __syncthreads();

    float acc1[2][4][4], acc2[2][4][4];
    #pragma unroll
    for (int mt = 0; mt < 2; ++mt)
        #pragma unroll
        for (int nt = 0; nt < 4; ++nt)
            #pragma unroll
            for (int j = 0; j < 4; ++j) { acc1[mt][nt][j] = 0.f; acc2[mt][nt][j] = 0.f; }

    #pragma unroll
    for (int kc = 0; kc < 8; ++kc) {
        unsigned ah[2][4], al[2][4];
        #pragma unroll
        for (int mt = 0; mt < 2; ++mt) {
            int r = wm*32 + mt*16 + gid;
            int ao = r*WSH + kc*16 + 2*tig;
            ah[mt][0] = *(const unsigned*)(AH + ao);
            ah[mt][1] = *(const unsigned*)(AH + ao + 8*WSH);
            ah[mt][2] = *(const unsigned*)(AH + ao + 8);
            ah[mt][3] = *(const unsigned*)(AH + ao + 8*WSH + 8);
            al[mt][0] = *(const unsigned*)(AL + ao);
            al[mt][1] = *(const unsigned*)(AL + ao + 8*WSH);
            al[mt][2] = *(const unsigned*)(AL + ao + 8);
            al[mt][3] = *(const unsigned*)(AL + ao + 8*WSH + 8);
        }
        #pragma unroll
        for (int nt = 0; nt < 4; ++nt) {
            int o = wn*32 + nt*8 + gid;
            int bo = o*WSH + kc*16 + 2*tig;
            unsigned a_h0 = *(const unsigned*)(W0H + bo);
            unsigned a_h1 = *(const unsigned*)(W0H + bo + 8);
            unsigned a_l0 = *(const unsigned*)(W0L + bo);
            unsigned a_l1 = *(const unsigned*)(W0L + bo + 8);
            unsigned b_h0 = *(const unsigned*)(W1H + bo);
            unsigned b_h1 = *(const unsigned*)(W1H + bo + 8);
            unsigned b_l0 = *(const unsigned*)(W1L + bo);
            unsigned b_l1 = *(const unsigned*)(W1L + bo + 8);
            #pragma unroll
            for (int mt = 0; mt < 2; ++mt) {
                mma16(acc1[mt][nt], ah[mt], a_h0, a_h1);
                mma16(acc1[mt][nt], ah[mt], a_l0, a_l1);
                mma16(acc1[mt][nt], al[mt], a_h0, a_h1);
                mma16(acc2[mt][nt], ah[mt], b_h0, b_h1);
                mma16(acc2[mt][nt], ah[mt], b_l0, b_l1);
                mma16(acc2[mt][nt], al[mt], b_h0, b_h1);
            }
        }
    }

    #pragma unroll
    for (int mt = 0; mt < 2; ++mt) {
        int rL = p0 + wm*32 + mt*16 + gid;
        #pragma unroll
        for (int nt = 0; nt < 4; ++nt) {
            int c = wn*32 + nt*8 + 2*tig;
            *(float2*)(t1 + (size_t)rL*NC + c)     = make_float2(acc1[mt][nt][0], acc1[mt][nt][1]);
            *(float2*)(t1 + (size_t)(rL+8)*NC + c) = make_float2(acc1[mt][nt][2], acc1[mt][nt][3]);
            *(float2*)(t2 + (size_t)rL*NC + c)     = make_float2(acc2[mt][nt][0], acc2[mt][nt][1]);
            *(float2*)(t2 + (size_t)(rL+8)*NC + c) = make_float2(acc2[mt][nt][2], acc2[mt][nt][3]);
        }
    }

    __syncthreads();
    stage_w(g_Wvhi, W0H, tid);
    stage_w(g_Wvlo, W0L, tid);
    __syncthreads();

    #pragma unroll
    for (int mt = 0; mt < 2; ++mt)
        #pragma unroll
        for (int nt = 0; nt < 4; ++nt)
            #pragma unroll
            for (int j = 0; j < 4; ++j) acc1[mt][nt][j] = 0.f;

    #pragma unroll
    for (int kc = 0; kc < 8; ++kc) {
        unsigned ah[2][4], al[2][4];
        #pragma unroll
        for (int mt = 0; mt < 2; ++mt) {
            int r = wm*32 + mt*16 + gid;
            int ao = r*WSH + kc*16 + 2*tig;
            ah[mt][0] = *(const unsigned*)(AH + ao);
            ah[mt][1] = *(const unsigned*)(AH + ao + 8*WSH);
            ah[mt][2] = *(const unsigned*)(AH + ao + 8);
            ah[mt][3] = *(const unsigned*)(AH + ao + 8*WSH + 8);
            al[mt][0] = *(const unsigned*)(AL + ao);
            al[mt][1] = *(const unsigned*)(AL + ao + 8*WSH);
            al[mt][2] = *(const unsigned*)(AL + ao + 8);
            al[mt][3] = *(const unsigned*)(AL + ao + 8*WSH + 8);
        }
        #pragma unroll
        for (int nt = 0; nt < 4; ++nt) {
            int o = wn*32 + nt*8 + gid;
            int bo = o*WSH + kc*16 + 2*tig;
            unsigned bh0 = *(const unsigned*)(W0H + bo);
            unsigned bh1 = *(const unsigned*)(W0H + bo + 8);
            unsigned bl0 = *(const unsigned*)(W0L + bo);
            unsigned bl1 = *(const unsigned*)(W0L + bo + 8);
            #pragma unroll
            for (int mt = 0; mt < 2; ++mt) {
                mma16(acc1[mt][nt], ah[mt], bh0, bh1);
                mma16(acc1[mt][nt], ah[mt], bl0, bl1);
                mma16(acc1[mt][nt], al[mt], bh0, bh1);
            }
        }
    }
    #pragma unroll
    for (int mt = 0; mt < 2; ++mt) {
        int rL = p0 + wm*32 + mt*16 + gid;
        #pragma unroll
        for (int nt = 0; nt < 4; ++nt) {
            int c = wn*32 + nt*8 + 2*tig;
            *(float2*)(vf + (size_t)rL*NC + c)     = make_float2(acc1[mt][nt][0], acc1[mt][nt][1]);
            *(float2*)(vf + (size_t)(rL+8)*NC + c) = make_float2(acc1[mt][nt][2], acc1[mt][nt][3]);
        }
    }
}

// ---------------- fused_main: bf16x3 m16n8k16 tensor cores ----------------
__global__ __launch_bounds__(512, 1) void fused_main(
    const float* __restrict__ xyz, const float* __restrict__ pb2,
    float* __restrict__ outpre)
{
    extern __shared__ char smc[];
    unsigned short* AH  = (unsigned short*)(smc);
    unsigned short* AL  = (unsigned short*)(smc + SLAB);
    unsigned short* W0H = (unsigned short*)(smc + 2*SLAB);
    unsigned short* W0L = (unsigned short*)(smc + 3*SLAB);
    unsigned short* W1H = (unsigned short*)(smc + 4*SLAB);
    unsigned short* W1L = (unsigned short*)(smc + 5*SLAB);
    int*   nid = (int*)(smc + 6*SLAB);
    float* rel = (float*)(smc + 6*SLAB + 512);

    int tid = threadIdx.x;
    int lane = tid & 31, wid = tid >> 5;
    int gid = lane >> 2, tig = lane & 3;
    int wm = wid & 3, wn = wid >> 2;
    int p0 = blockIdx.x * 8;

    if (tid < 128) {
        int r = tid;
        int p = p0 + (r >> 4);
        int g = g_idx[(size_t)p*NK + (r & 15)];
        nid[r] = g;
        rel[r*3+0] = xyz[(size_t)g*3+0] - xyz[(size_t)p*3+0];
        rel[r*3+1] = xyz[(size_t)g*3+1] - xyz[(size_t)p*3+1];
        rel[r*3+2] = xyz[(size_t)g*3+2] - xyz[(size_t)p*3+2];
    }
    __syncthreads();

    {   // u = relu(pW1'*rel + b1'), split to bf16 hi/lo slabs
        int c = tid & 127;
        int r0 = tid >> 7;
        float w0 = g_pW1s[c*3+0], w1 = g_pW1s[c*3+1], w2 = g_pW1s[c*3+2];
        float bb = g_b1p[c];
        #pragma unroll
        for (int r = r0; r < 128; r += 4) {
            float v = fmaf(w0, rel[r*3+0], fmaf(w1, rel[r*3+1], fmaf(w2, rel[r*3+2], bb)));
            v = fmaxf(v, 0.f);
            __nv_bfloat16 bh = __float2bfloat16_rn(v);
            AH[r*WSH + c] = __bfloat16_as_ushort(bh);
            AL[r*WSH + c] = __bfloat16_as_ushort(__float2bfloat16_rn(v - __bfloat162float(bh)));
        }
    }

    stage_w(g_W3hi,  W0H, tid);
    stage_w(g_W3lo,  W0L, tid);
    stage_w(g_pW2hi, W1H, tid);
    stage_w(g_pW2lo, W1L, tid);
    __syncthreads();

    float acc1[2][4][4], acc2[2][4][4];
    #pragma unroll
    for (int mt = 0; mt < 2; ++mt)
        #pragma unroll
        for (int nt = 0; nt < 4; ++nt)
            #pragma unroll
            for (int j = 0; j < 4; ++j) { acc1[mt][nt][j] = 0.f; acc2[mt][nt][j] = 0.f; }

    // fused GEMM1a (W3') + GEMM1b (pW2), shared A = u
    #pragma unroll
    for (int kc = 0; kc < 8; ++kc) {
        unsigned ah[2][4], al[2][4];
        #pragma unroll
        for (int mt = 0; mt < 2; ++mt) {
            int r = wm*32 + mt*16 + gid;
            int ao = r*WSH + kc*16 + 2*tig;
            ah[mt][0] = *(const unsigned*)(AH + ao);
            ah[mt][1] = *(const unsigned*)(AH + ao + 8*WSH);
            ah[mt][2] = *(const unsigned*)(AH + ao + 8);
            ah[mt][3] = *(const unsigned*)(AH + ao + 8*WSH + 8);
            al[mt][0] = *(const unsigned*)(AL + ao);
            al[mt][1] = *(const unsigned*)(AL + ao + 8*WSH);
            al[mt][2] = *(const unsigned*)(AL + ao + 8);
            al[mt][3] = *(const unsigned*)(AL + ao + 8*WSH + 8);
        }
        #pragma unroll
        for (int nt = 0; nt < 4; ++nt) {
            int o = wn*32 + nt*8 + gid;
            int bo = o*WSH + kc*16 + 2*tig;
            unsigned w3h0 = *(const unsigned*)(W0H + bo);
            unsigned w3h1 = *(const unsigned*)(W0H + bo + 8);
            unsigned w3l0 = *(const unsigned*)(W0L + bo);
            unsigned w3l1 = *(const unsigned*)(W0L + bo + 8);
            unsigned p2h0 = *(const unsigned*)(W1H + bo);
            unsigned p2h1 = *(const unsigned*)(W1H + bo + 8);
            unsigned p2l0 = *(const unsigned*)(W1L + bo);
            unsigned p2l1 = *(const unsigned*)(W1L + bo + 8);
            #pragma unroll
            for (int mt = 0; mt < 2; ++mt) {
                mma16(acc1[mt][nt], ah[mt], w3h0, w3h1);
                mma16(acc1[mt][nt], ah[mt], w3l0, w3l1);
                mma16(acc1[mt][nt], al[mt], w3h0, w3h1);
                mma16(acc2[mt][nt], ah[mt], p2h0, p2h1);
                mma16(acc2[mt][nt], ah[mt], p2l0, p2l1);
                mma16(acc2[mt][nt], al[mt], p2h0, p2h1);
            }
        }
    }
    __syncthreads();

    // epilogue 1: h = relu(acc1 + t1[p] - t2[g] + cc) -> AH/AL
    #pragma unroll
    for (int mt = 0; mt < 2; ++mt) {
        int rL = wm*32 + mt*16 + gid;
        int p = p0 + wm*2 + mt;
        int g0 = nid[rL], g1 = nid[rL+8];
        #pragma unroll
        for (int nt = 0; nt < 4; ++nt) {
            int c = wn*32 + nt*8 + 2*tig;
            float2 t1v = *(const float2*)(g_t1 + (size_t)p*NC + c);
            float2 ccv = *(const float2*)(g_cc + c);
            float2 t20 = *(const float2*)(g_t2 + (size_t)g0*NC + c);
            float2 t21 = *(const float2*)(g_t2 + (size_t)g1*NC + c);
            float h00 = fmaxf(acc1[mt][nt][0] + t1v.x - t20.x + ccv.x, 0.f);
            float h01 = fmaxf(acc1[mt][nt][1] + t1v.y - t20.y + ccv.y, 0.f);
            float h10 = fmaxf(acc1[mt][nt][2] + t1v.x - t21.x + ccv.x, 0.f);
            float h11 = fmaxf(acc1[mt][nt][3] + t1v.y - t21.y + ccv.y, 0.f);
            unsigned hi, lo;
            split2(h00, h01, hi, lo);
            *(unsigned*)(AH + rL*WSH + c) = hi;
            *(unsigned*)(AL + rL*WSH + c) = lo;
            split2(h10, h11, hi, lo);
            *(unsigned*)(AH + (rL+8)*WSH + c) = hi;
            *(unsigned*)(AL + (rL+8)*WSH + c) = lo;
        }
    }

    // epilogue 2: pvr = acc2 + pb2 + vf[g]
    float pvr[2][4][4];
    #pragma unroll
    for (int mt = 0; mt < 2; ++mt) {
        int rL = wm*32 + mt*16 + gid;
        int g0 = nid[rL], g1 = nid[rL+8];
        #pragma unroll
        for (int nt = 0; nt < 4; ++nt) {
            int c = wn*32 + nt*8 + 2*tig;
            float2 pbv = *(const float2*)(pb2 + c);
            float2 v0 = *(const float2*)(g_vf + (size_t)g0*NC + c);
            float2 v1 = *(const float2*)(g_vf + (size_t)g1*NC + c);
            pvr[mt][nt][0] = acc2[mt][nt][0] + pbv.x + v0.x;
            pvr[mt][nt][1] = acc2[mt][nt][1] + pbv.y + v0.y;
            pvr[mt][nt][2] = acc2[mt][nt][2] + pbv.x + v1.x;
            pvr[mt][nt][3] = acc2[mt][nt][3] + pbv.y + v1.y;
        }
    }

    stage_w(g_aW2hi, W0H, tid);
    stage_w(g_aW2lo, W0L, tid);
    __syncthreads();

    // GEMM2: logits = h @ aW2^T  (ab2 cancels in softmax)
    #pragma unroll
    for (int mt = 0; mt < 2; ++mt)
        #pragma unroll
        for (int nt = 0; nt < 4; ++nt)
            #pragma unroll
            for (int j = 0; j < 4; ++j) acc1[mt][nt][j] = 0.f;

    #pragma unroll
    for (int kc = 0; kc < 8; ++kc) {
        unsigned ah[2][4], al[2][4];
        #pragma unroll
        for (int mt = 0; mt < 2; ++mt) {
            int r = wm*32 + mt*16 + gid;
            int ao = r*WSH + kc*16 + 2*tig;
            ah[mt][0] = *(const unsigned*)(AH + ao);
            ah[mt][1] = *(const unsigned*)(AH + ao + 8*WSH);
            ah[mt][2] = *(const unsigned*)(AH + ao + 8);
            ah[mt][3] = *(const unsigned*)(AH + ao + 8*WSH + 8);
            al[mt][0] = *(const unsigned*)(AL + ao);
            al[mt][1] = *(const unsigned*)(AL + ao + 8*WSH);
            al[mt][2] = *(const unsigned*)(AL + ao + 8);
            al[mt][3] = *(const unsigned*)(AL + ao + 8*WSH + 8);
        }
        #pragma unroll
        for (int nt = 0; nt < 4; ++nt) {
            int o = wn*32 + nt*8 + gid;
            int bo = o*WSH + kc*16 + 2*tig;
            unsigned bh0 = *(const unsigned*)(W0H + bo);
            unsigned bh1 = *(const unsigned*)(W0H + bo + 8);
            unsigned bl0 = *(const unsigned*)(W0L + bo);
            unsigned bl1 = *(const unsigned*)(W0L + bo + 8);
            #pragma unroll
            for (int mt = 0; mt < 2; ++mt) {
                mma16(acc1[mt][nt], ah[mt], bh0, bh1);
                mma16(acc1[mt][nt], ah[mt], bl0, bl1);
                mma16(acc1[mt][nt], al[mt], bh0, bh1);
            }
        }
    }

    // softmax over K + weighted reduce, in registers
    #pragma unroll
    for (int mt = 0; mt < 2; ++mt) {
        int p = p0 + wm*2 + mt;
        #pragma unroll
        for (int nt = 0; nt < 4; ++nt) {
            #pragma unroll
            for (int j = 0; j < 2; ++j) {
                float x0 = acc1[mt][nt][j], x1 = acc1[mt][nt][2+j];
                float m = fmaxf(x0, x1);
                m = fmaxf(m, __shfl_xor_sync(0xffffffffu, m, 4));
                m = fmaxf(m, __shfl_xor_sync(0xffffffffu, m, 8));
                m = fmaxf(m, __shfl_xor_sync(0xffffffffu, m, 16));
                float e0 = __expf(x0 - m), e1 = __expf(x1 - m);
                float s = e0 + e1;
                float a = fmaf(e0, pvr[mt][nt][j], e1 * pvr[mt][nt][2+j]);
                s += __shfl_xor_sync(0xffffffffu, s, 4);
                a += __shfl_xor_sync(0xffffffffu, a, 4);
                s += __shfl_xor_sync(0xffffffffu, s, 8);
                a += __shfl_xor_sync(0xffffffffu, a, 8);
                s += __shfl_xor_sync(0xffffffffu, s, 16);
                a += __shfl_xor_sync(0xffffffffu, a, 16);
                if (gid == 0)
                    outpre[(size_t)p*NC + wn*32 + nt*8 + 2*tig + j] = a / s;
            }
        }
    }
}

// ---------------- final GEMM (Wout, scalar) ----------------
__global__ __launch_bounds__(256) void gemm_rt(
    const float* __restrict__ A, const float* __restrict__ Wt, float* __restrict__ out)
{
    extern __shared__ float sm[];
    float* AS  = sm;
    float* WTs = AS + NC*SA;

    int tid = threadIdx.x, tx = tid & 15, ty = tid >> 4;
    int p0 = blockIdx.x * 128;

    #pragma unroll
    for (int it = 0; it < 16; ++it) {
        int e = (it*256 + tid) * 4;
        int r = e >> 7, c = e & 127;
        *(float4*)(AS + r*SA + c) = *(const float4*)(A + (size_t)(p0 + r)*NC + c);
    }

    float acc[8][8];
    #pragma unroll
    for (int ir = 0; ir < 8; ++ir)
        #pragma unroll
        for (int io = 0; io < 8; ++io) acc[ir][io] = 0.f;

    #pragma unroll 1
    for (int k0 = 0; k0 < NC; k0 += 16) {
        __syncthreads();
        int e = tid * 8;
        *(float4*)(WTs + e)     = *(const float4*)(Wt + k0*NC + e);
        *(float4*)(WTs + e + 4) = *(const float4*)(Wt + k0*NC + e + 4);
        __syncthreads();
        #pragma unroll
        for (int kk = 0; kk < 16; ++kk) {
            float wf[8];
            ((float4*)wf)[0] = *(const float4*)(WTs + kk*NC + tx*8);
            ((float4*)wf)[1] = *(const float4*)(WTs + kk*NC + tx*8 + 4);
            float af[8];
            #pragma unroll
            for (int ir = 0; ir < 8; ++ir) af[ir] = AS[(ty*8 + ir)*SA + k0 + kk];
            #pragma unroll
            for (int ir = 0; ir < 8; ++ir)
                #pragma unroll
                for (int io = 0; io < 8; ++io)
                    acc[ir][io] = fmaf(af[ir], wf[io], acc[ir][io]);
        }
    }

    #pragma unroll
    for (int ir = 0; ir < 8; ++ir) {
        int r = p0 + ty*8 + ir;
        #pragma unroll
        for (int io4 = 0; io4 < 8; io4 += 4) {
            float4 v;
            v.x = acc[ir][io4+0]; v.y = acc[ir][io4+1];
            v.z = acc[ir][io4+2]; v.w = acc[ir][io4+3];
            *(float4*)(out + (size_t)r*NC + tx*8 + io4) = v;
        }
    }
}

// ---------------- launch ----------------
#define GEMM_SMEM  ((NC*SA + 16*NC) * 4)
#define G3_SMEM    (6*SLAB)
#define MAIN_SMEM  (6*SLAB + 512 + NC*3*4)

extern "C" void kernel_launch(void* const* d_in, const int* in_sizes, int n_in,
                              void* d_out, int out_size)
{
    const float* xyz   = (const float*)d_in[0];
    const float* feat  = (const float*)d_in[1];
    const float* Wq    = (const float*)d_in[2];
    const float* Wk    = (const float*)d_in[3];
    const float* Wv    = (const float*)d_in[4];
    const float* pW1   = (const float*)d_in[5];
    const float* pb1   = (const float*)d_in[6];
    const float* pg    = (const float*)d_in[7];
    const float* pbeta = (const float*)d_in[8];
    const float* pmean = (const float*)d_in[9];
    const float* pvar  = (const float*)d_in[10];
    const float* pW2   = (const float*)d_in[11];
    const float* pb2   = (const float*)d_in[12];
    const float* aW1   = (const float*)d_in[13];
    const float* ab1   = (const float*)d_in[14];
    const float* ag    = (const float*)d_in[15];
    const float* abeta = (const float*)d_in[16];
    const float* amean = (const float*)d_in[17];
    const float* avar  = (const float*)d_in[18];
    const float* aW2   = (const float*)d_in[19];
    const float* ab2   = (const float*)d_in[20];  (void)ab2;
    const float* Wout  = (const float*)d_in[21];
    float* out = (float*)d_out;

    void *p_t1, *p_t2, *p_vf, *p_outpre, *p_idx, *p_pd, *p_pi, *p_Woutt;
    cudaGetSymbolAddress(&p_t1, g_t1);
    cudaGetSymbolAddress(&p_t2, g_t2);
    cudaGetSymbolAddress(&p_vf, g_vf);
    cudaGetSymbolAddress(&p_outpre, g_outpre);
    cudaGetSymbolAddress(&p_idx, g_idx);
    cudaGetSymbolAddress(&p_pd, g_pd);
    cudaGetSymbolAddress(&p_pi, g_pi);
    cudaGetSymbolAddress(&p_Woutt, g_Woutt);

    cudaFuncSetAttribute(gemm_rt,    cudaFuncAttributeMaxDynamicSharedMemorySize, GEMM_SMEM);
    cudaFuncSetAttribute(gemm3_tc,   cudaFuncAttributeMaxDynamicSharedMemorySize, G3_SMEM);
    cudaFuncSetAttribute(fused_main, cudaFuncAttributeMaxDynamicSharedMemorySize, MAIN_SMEM);

    setup_kernel<<<NC, NC>>>(Wq, Wk, Wv, pW1, pb1, pg, pbeta, pmean, pvar,
                             pW2, pb2, aW1, ab1, ag, abeta, amean, avar, aW2, Wout);

    knn_part<<<dim3(NP/256, KSPLIT), 128>>>(xyz, (float*)p_pd, (int*)p_pi);
    knn_merge<<<NP/128, 128>>>((const float*)p_pd, (const int*)p_pi, (int*)p_idx);

    gemm3_tc<<<NP/128, 512, G3_SMEM>>>(feat, (float*)p_t1, (float*)p_t2, (float*)p_vf);

    fused_main<<<NP/8, 512, MAIN_SMEM>>>(xyz, pb2, (float*)p_outpre);

    gemm_rt<<<NP/128, 256, GEMM_SMEM>>>((const float*)p_outpre, (const float*)p_Woutt, out);
}

// round 14
// speedup vs baseline: 3.2054x; 1.0336x over previous
#include <cuda_runtime.h>
#include <cuda_bf16.h>
#include <math.h>
#include <stdint.h>

#define NB 2
#define NN 8192
#define NC 128
#define NK 16
#define NP (NB*NN)
#define EPSF 1e-5f
#define SA 132
#define WSH 136              // packed-slab row stride in ushorts (128 + 8 pad)
#define SLAB (NC*WSH*2)      // slab bytes = 34816
#define KSPLIT 8
#define KCH (NN/KSPLIT)      // 1024 candidates per chunk

__device__ float g_t1[NP*NC];
__device__ float g_t2[NP*NC];
__device__ float g_vf[NP*NC];
__device__ float g_outpre[NP*NC];
__device__ int   g_idx[NP*NK];
__device__ float g_pd[NP*KSPLIT*NK];
__device__ int   g_pi[NP*KSPLIT*NK];

__device__ float g_Woutt[NC*NC];
__device__ float g_cc[NC];
__device__ float g_pW1s[NC*3];
__device__ float g_b1p[NC];

// bf16 hi/lo weight splits, [o][k] row-major ushorts
__device__ unsigned short g_Athi[NC*NC], g_Atlo[NC*NC];
__device__ unsigned short g_Bthi[NC*NC], g_Btlo[NC*NC];
__device__ unsigned short g_Wvhi[NC*NC], g_Wvlo[NC*NC];
__device__ unsigned short g_W3hi[NC*NC],  g_W3lo[NC*NC];
__device__ unsigned short g_pW2hi[NC*NC], g_pW2lo[NC*NC];
__device__ unsigned short g_aW2hi[NC*NC], g_aW2lo[NC*NC];

__device__ __forceinline__ void mma16(float* d, const unsigned* a, unsigned b0, unsigned b1) {
    asm volatile("mma.sync.aligned.m16n8k16.row.col.f32.bf16.bf16.f32 "
        "{%0,%1,%2,%3}, {%4,%5,%6,%7}, {%8,%9}, {%0,%1,%2,%3};"
        : "+f"(d[0]), "+f"(d[1]), "+f"(d[2]), "+f"(d[3])
        : "r"(a[0]), "r"(a[1]), "r"(a[2]), "r"(a[3]), "r"(b0), "r"(b1));
}

// ---- packed f32x2 helpers (sm_100+): two fmaf.rn in one instruction, bit-exact ----
__device__ __forceinline__ unsigned long long pk2(float x) {
    unsigned long long r; asm("mov.b64 %0, {%1, %1};" : "=l"(r) : "f"(x)); return r;
}
__device__ __forceinline__ unsigned long long fma2(unsigned long long a, unsigned long long b,
                                                   unsigned long long c) {
    unsigned long long d;
    asm("fma.rn.f32x2 %0, %1, %2, %3;" : "=l"(d) : "l"(a), "l"(b), "l"(c));
    return d;
}
__device__ __forceinline__ float2 up2(unsigned long long v) {
    float2 f; asm("mov.b64 {%0, %1}, %2;" : "=f"(f.x), "=f"(f.y) : "l"(v)); return f;
}

// split two fp32 into packed bf16x2 hi and lo words (x0 in low half)
__device__ __forceinline__ void split2(float x0, float x1, unsigned& hi, unsigned& lo) {
    __nv_bfloat16 h0 = __float2bfloat16_rn(x0), h1 = __float2bfloat16_rn(x1);
    float r0 = x0 - __bfloat162float(h0);
    float r1 = x1 - __bfloat162float(h1);
    __nv_bfloat16 l0 = __float2bfloat16_rn(r0), l1 = __float2bfloat16_rn(r1);
    hi = ((unsigned)__bfloat16_as_ushort(h1) << 16) | (unsigned)__bfloat16_as_ushort(h0);
    lo = ((unsigned)__bfloat16_as_ushort(l1) << 16) | (unsigned)__bfloat16_as_ushort(l0);
}
__device__ __forceinline__ void splitw(float x, unsigned short* hi, unsigned short* lo, int idx) {
    __nv_bfloat16 b = __float2bfloat16_rn(x);
    hi[idx] = __bfloat16_as_ushort(b);
    lo[idx] = __bfloat16_as_ushort(__float2bfloat16_rn(x - __bfloat162float(b)));
}

// ---------------- setup ----------------
__global__ void setup_kernel(
    const float* __restrict__ Wq, const float* __restrict__ Wk,
    const float* __restrict__ Wv, const float* __restrict__ pW1,
    const float* __restrict__ pb1, const float* __restrict__ pg,
    const float* __restrict__ pbeta, const float* __restrict__ pmean,
    const float* __restrict__ pvar, const float* __restrict__ pW2,
    const float* __restrict__ pb2, const float* __restrict__ aW1,
    const float* __restrict__ ab1, const float* __restrict__ ag,
    const float* __restrict__ abeta, const float* __restrict__ amean,
    const float* __restrict__ avar, const float* __restrict__ aW2,
    const float* __restrict__ Wout)
{
    __shared__ float arow[NC];
    int o = blockIdx.x, i = threadIdx.x;
    arow[i] = aW1[o*NC + i];
    __syncthreads();
    float s2o = ag[o] * rsqrtf(avar[o] + EPSF);
    float sA = 0.f, sB = 0.f, sW = 0.f;
    #pragma unroll 4
    for (int m = 0; m < NC; ++m) {
        float a = arow[m];
        sA = fmaf(a, Wq[m*NC + i], sA);
        sB = fmaf(a, Wk[m*NC + i], sB);
        sW = fmaf(a, pW2[m*NC + i], sW);
    }
    g_Woutt[i*NC + o] = Wout[o*NC + i];

    int e = o*NC + i;
    splitw(s2o * sA, g_Athi, g_Atlo, e);
    splitw(s2o * sB, g_Bthi, g_Btlo, e);
    splitw(Wv[e],    g_Wvhi, g_Wvlo, e);
    splitw(s2o * sW, g_W3hi, g_W3lo, e);
    splitw(pW2[e],   g_pW2hi, g_pW2lo, e);
    splitw(aW2[e],   g_aW2hi, g_aW2lo, e);

    if (o == 0) {
        int c = i;
        float s1 = pg[c] * rsqrtf(pvar[c] + EPSF);
        g_pW1s[c*3+0] = pW1[c*3+0] * s1;
        g_pW1s[c*3+1] = pW1[c*3+1] * s1;
        g_pW1s[c*3+2] = pW1[c*3+2] * s1;
        g_b1p[c] = (pb1[c] - pmean[c]) * s1 + pbeta[c];
        float s2c = ag[c] * rsqrtf(avar[c] + EPSF);
        float c0 = ab1[c];
        for (int m = 0; m < NC; ++m) c0 = fmaf(aW1[c*NC + m], pb2[m], c0);
        g_cc[c] = s2c * c0 + abeta[c] - amean[c] * s2c;
    }
}

// ---------------- KNN stage 1 (scalar, KSPLIT=8, packed f32x2 distances) ----------------
__device__ __forceinline__ void ins16(float d, int m, float bd[NK], int bi[NK]) {
    if (d < bd[NK-1]) {
        bd[NK-1] = d; bi[NK-1] = m;
        #pragma unroll
        for (int s = NK-1; s >= 1; --s) {
            if (bd[s] < bd[s-1]) {
                float td = bd[s]; bd[s] = bd[s-1]; bd[s-1] = td;
                int   ti = bi[s]; bi[s] = bi[s-1]; bi[s-1] = ti;
            }
        }
    }
}

__global__ __launch_bounds__(128) void knn_part(
    const float* __restrict__ xyz, float* __restrict__ pd, int* __restrict__ pi)
{
    __shared__ __align__(16) float cx[256];
    __shared__ __align__(16) float cy[256];
    __shared__ __align__(16) float cz[256];
    __shared__ __align__(16) float cw[256];

    int tid = threadIdx.x;
    int qA = blockIdx.x * 256 + tid;
    int qB = qA + 128;
    int base = (qA / NN) * NN;
    int c0 = base + blockIdx.y * KCH;

    float nax = -2.f*xyz[(size_t)qA*3+0], nay = -2.f*xyz[(size_t)qA*3+1], naz = -2.f*xyz[(size_t)qA*3+2];
    float nbx = -2.f*xyz[(size_t)qB*3+0], nby = -2.f*xyz[(size_t)qB*3+1], nbz = -2.f*xyz[(size_t)qB*3+2];
    unsigned long long pax = pk2(nax), pay = pk2(nay), paz = pk2(naz);
    unsigned long long pbx = pk2(nbx), pby = pk2(nby), pbz = pk2(nbz);

    float bdA[NK], bdB[NK]; int biA[NK], biB[NK];
    #pragma unroll
    for (int k = 0; k < NK; ++k) {
        bdA[k] = INFINITY; biA[k] = 0;
        bdB[k] = INFINITY; biB[k] = 0;
    }

    for (int t0 = 0; t0 < KCH; t0 += 256) {
        __syncthreads();
        #pragma unroll
        for (int j = tid; j < 256; j += 128) {
            int m = c0 + t0 + j;
            float x = xyz[(size_t)m*3+0], y = xyz[(size_t)m*3+1], z = xyz[(size_t)m*3+2];
            cx[j] = x; cy[j] = y; cz[j] = z;
            cw[j] = fmaf(x, x, fmaf(y, y, z*z));
        }
        __syncthreads();
        #pragma unroll 2
        for (int j = 0; j < 256; j += 4) {
            ulonglong2 X = *(const ulonglong2*)(cx + j);
            ulonglong2 Y = *(const ulonglong2*)(cy + j);
            ulonglong2 Z = *(const ulonglong2*)(cz + j);
            ulonglong2 W = *(const ulonglong2*)(cw + j);

            float2 a01 = up2(fma2(pax, X.x, fma2(pay, Y.x, fma2(paz, Z.x, W.x))));
            float2 a23 = up2(fma2(pax, X.y, fma2(pay, Y.y, fma2(paz, Z.y, W.y))));
            if (fminf(fminf(a01.x, a01.y), fminf(a23.x, a23.y)) < bdA[NK-1]) {
                ins16(a01.x, t0+j,   bdA, biA);
                ins16(a01.y, t0+j+1, bdA, biA);
                ins16(a23.x, t0+j+2, bdA, biA);
                ins16(a23.y, t0+j+3, bdA, biA);
            }

            float2 b01 = up2(fma2(pbx, X.x, fma2(pby, Y.x, fma2(pbz, Z.x, W.x))));
            float2 b23 = up2(fma2(pbx, X.y, fma2(pby, Y.y, fma2(pbz, Z.y, W.y))));
            if (fminf(fminf(b01.x, b01.y), fminf(b23.x, b23.y)) < bdB[NK-1]) {
                ins16(b01.x, t0+j,   bdB, biB);
                ins16(b01.y, t0+j+1, bdB, biB);
                ins16(b23.x, t0+j+2, bdB, biB);
                ins16(b23.y, t0+j+3, bdB, biB);
            }
        }
    }
    size_t oA = (size_t)qA*(KSPLIT*NK) + blockIdx.y*NK;
    size_t oB = (size_t)qB*(KSPLIT*NK) + blockIdx.y*NK;
    #pragma unroll
    for (int k = 0; k < NK; ++k) {
        pd[oA+k] = bdA[k]; pi[oA+k] = c0 + biA[k];
        pd[oB+k] = bdB[k]; pi[oB+k] = c0 + biB[k];
    }
}

// ---------------- KNN stage 2: merge ----------------
__global__ __launch_bounds__(128) void knn_merge(
    const float* __restrict__ pd, const int* __restrict__ pi, int* __restrict__ idxo)
{
    int q = blockIdx.x * 128 + threadIdx.x;
    float bd[NK]; int bi[NK];
    #pragma unroll
    for (int k = 0; k < NK; ++k) { bd[k] = INFINITY; bi[k] = 0x7fffffff; }
    size_t ib = (size_t)q * (KSPLIT*NK);
    for (int j = 0; j < KSPLIT*NK; ++j) {
        float d = pd[ib + j];
        int   m = pi[ib + j];
        if (d < bd[NK-1] || (d == bd[NK-1] && m < bi[NK-1])) {
            bd[NK-1] = d; bi[NK-1] = m;
            #pragma unroll
            for (int s = NK-1; s >= 1; --s) {
                bool sw = (bd[s] < bd[s-1]) || (bd[s] == bd[s-1] && bi[s] < bi[s-1]);
                if (sw) {
                    float td = bd[s]; bd[s] = bd[s-1]; bd[s-1] = td;
                    int   ti = bi[s]; bi[s] = bi[s-1]; bi[s-1] = ti;
                }
            }
        }
    }
    #pragma unroll
    for (int k = 0; k < NK; ++k) idxo[(size_t)q*NK + k] = bi[k];
}

// ---------------- stage a 128x128 ushort weight matrix into a smem slab ----------------
__device__ __forceinline__ void stage_w(const unsigned short* __restrict__ g,
                                        unsigned short* s, int tid)
{
    int row = tid >> 2, q = tid & 3;
    #pragma unroll
    for (int j = 0; j < 4; ++j)
        *(uint4*)(s + row*WSH + q*32 + j*8) = *(const uint4*)(g + row*NC + q*32 + j*8);
}

// ---------------- gemm3_tc: t1/t2/vf via bf16x3 tensor cores ----------------
__global__ __launch_bounds__(512, 1) void gemm3_tc(
    const float* __restrict__ feat, float* __restrict__ t1,
    float* __restrict__ t2, float* __restrict__ vf)
{
    extern __shared__ char smc[];
    unsigned short* AH  = (unsigned short*)(smc);
    unsigned short* AL  = (unsigned short*)(smc + SLAB);
    unsigned short* W0H = (unsigned short*)(smc + 2*SLAB);
    unsigned short* W0L = (unsigned short*)(smc + 3*SLAB);
    unsigned short* W1H = (unsigned short*)(smc + 4*SLAB);
    unsigned short* W1L = (unsigned short*)(smc + 5*SLAB);

    int tid = threadIdx.x;
    int lane = tid & 31, wid = tid >> 5;
    int gid = lane >> 2, tig = lane & 3;
    int wm = wid & 3, wn = wid >> 2;
    int p0 = blockIdx.x * 128;

    {
        int row = tid >> 2, q = tid & 3;
        const float* src = feat + (size_t)(p0 + row)*NC + q*32;
        #pragma unroll
        for (int j = 0; j < 32; j += 2) {
            float2 v = *(const float2*)(src + j);
            unsigned hi, lo;
            split2(v.x, v.y, hi, lo);
            *(unsigned*)(AH + row*WSH + q*32 + j) = hi;
            *(unsigned*)(AL + row*WSH + q*32 + j) = lo;
        }
    }
    stage_w(g_Athi, W0H, tid);
    stage_w(g_Atlo, W0L, tid);
    stage_w(g_Bthi, W1H, tid);
    stage_w(g_Btlo, W1L, tid);
    __syncthreads();

    float acc1[2][4][4], acc2[2][4][4];
    #pragma unroll
    for (int mt = 0; mt < 2; ++mt)
        #pragma unroll
        for (int nt = 0; nt < 4; ++nt)
            #pragma unroll
            for (int j = 0; j < 4; ++j) { acc1[mt][nt][j] = 0.f; acc2[mt][nt][j] = 0.f; }

    #pragma unroll
    for (int kc = 0; kc < 8; ++kc) {
        unsigned ah[2][4], al[2][4];
        #pragma unroll
        for (int mt = 0; mt < 2; ++mt) {
            int r = wm*32 + mt*16 + gid;
            int ao = r*WSH + kc*16 + 2*tig;
            ah[mt][0] = *(const unsigned*)(AH + ao);
            ah[mt][1] = *(const unsigned*)(AH + ao + 8*WSH);
            ah[mt][2] = *(const unsigned*)(AH + ao + 8);
            ah[mt][3] = *(const unsigned*)(AH + ao + 8*WSH + 8);
            al[mt][0] = *(const unsigned*)(AL + ao);
            al[mt][1] = *(const unsigned*)(AL + ao + 8*WSH);
            al[mt][2] = *(const unsigned*)(AL + ao + 8);
            al[mt][3] = *(const unsigned*)(AL + ao + 8*WSH + 8);
        }
        #pragma unroll
        for (int nt = 0; nt < 4; ++nt) {
            int o = wn*32 + nt*8 + gid;
            int bo = o*WSH + kc*16 + 2*tig;
            unsigned a_h0 = *(const unsigned*)(W0H + bo);
            unsigned a_h1 = *(const unsigned*)(W0H + bo + 8);
            unsigned a_l0 = *(const unsigned*)(W0L + bo);
            unsigned a_l1 = *(const unsigned*)(W0L + bo + 8);
            unsigned b_h0 = *(const unsigned*)(W1H + bo);
            unsigned b_h1 = *(const unsigned*)(W1H + bo + 8);
            unsigned b_l0 = *(const unsigned*)(W1L + bo);
            unsigned b_l1 = *(const unsigned*)(W1L + bo + 8);
            #pragma unroll
            for (int mt = 0; mt < 2; ++mt) {
                mma16(acc1[mt][nt], ah[mt], a_h0, a_h1);
                mma16(acc1[mt][nt], ah[mt], a_l0, a_l1);
                mma16(acc1[mt][nt], al[mt], a_h0, a_h1);
                mma16(acc2[mt][nt], ah[mt], b_h0, b_h1);
                mma16(acc2[mt][nt], ah[mt], b_l0, b_l1);
                mma16(acc2[mt][nt], al[mt], b_h0, b_h1);
            }
        }
    }

    #pragma unroll
    for (int mt = 0; mt < 2; ++mt) {
        int rL = p0 + wm*32 + mt*16 + gid;
        #pragma unroll
        for (int nt = 0; nt < 4; ++nt) {
            int c = wn*32 + nt*8 + 2*tig;
            *(float2*)(t1 + (size_t)rL*NC + c)     = make_float2(acc1[mt][nt][0], acc1[mt][nt][1]);
            *(float2*)(t1 + (size_t)(rL+8)*NC + c) = make_float2(acc1[mt][nt][2], acc1[mt][nt][3]);
            *(float2*)(t2 + (size_t)rL*NC + c)     = make_float2(acc2[mt][nt][0], acc2[mt][nt][1]);
            *(float2*)(t2 + (size_t)(rL+8)*NC + c) = make_float2(acc2[mt][nt][2], acc2[mt][nt][3]);
        }
    }

    __syncthreads();
    stage_w(g_Wvhi, W0H, tid);
    stage_w(g_Wvlo, W0L, tid);
    __syncthreads();

    #pragma unroll
    for (int mt = 0; mt < 2; ++mt)
        #pragma unroll
        for (int nt = 0; nt < 4; ++nt)
            #pragma unroll
            for (int j = 0; j < 4; ++j) acc1[mt][nt][j] = 0.f;

    #pragma unroll
    for (int kc = 0; kc < 8; ++kc) {
        unsigned ah[2][4], al[2][4];
        #pragma unroll
        for (int mt = 0; mt < 2; ++mt) {
            int r = wm*32 + mt*16 + gid;
            int ao = r*WSH + kc*16 + 2*tig;
            ah[mt][0] = *(const unsigned*)(AH + ao);
            ah[mt][1] = *(const unsigned*)(AH + ao + 8*WSH);
            ah[mt][2] = *(const unsigned*)(AH + ao + 8);
            ah[mt][3] = *(const unsigned*)(AH + ao + 8*WSH + 8);
            al[mt][0] = *(const unsigned*)(AL + ao);
            al[mt][1] = *(const unsigned*)(AL + ao + 8*WSH);
            al[mt][2] = *(const unsigned*)(AL + ao + 8);
            al[mt][3] = *(const unsigned*)(AL + ao + 8*WSH + 8);
        }
        #pragma unroll
        for (int nt = 0; nt < 4; ++nt) {
            int o = wn*32 + nt*8 + gid;
            int bo = o*WSH + kc*16 + 2*tig;
            unsigned bh0 = *(const unsigned*)(W0H + bo);
            unsigned bh1 = *(const unsigned*)(W0H + bo + 8);
            unsigned bl0 = *(const unsigned*)(W0L + bo);
            unsigned bl1 = *(const unsigned*)(W0L + bo + 8);
            #pragma unroll
            for (int mt = 0; mt < 2; ++mt) {
                mma16(acc1[mt][nt], ah[mt], bh0, bh1);
                mma16(acc1[mt][nt], ah[mt], bl0, bl1);
                mma16(acc1[mt][nt], al[mt], bh0, bh1);
            }
        }
    }
    #pragma unroll
    for (int mt = 0; mt < 2; ++mt) {
        int rL = p0 + wm*32 + mt*16 + gid;
        #pragma unroll
        for (int nt = 0; nt < 4; ++nt) {
            int c = wn*32 + nt*8 + 2*tig;
            *(float2*)(vf + (size_t)rL*NC + c)     = make_float2(acc1[mt][nt][0], acc1[mt][nt][1]);
            *(float2*)(vf + (size_t)(rL+8)*NC + c) = make_float2(acc1[mt][nt][2], acc1[mt][nt][3]);
        }
    }
}

// ---------------- fused_main: bf16x3 m16n8k16 tensor cores ----------------
__global__ __launch_bounds__(512, 1) void fused_main(
    const float* __restrict__ xyz, const float* __restrict__ pb2,
    float* __restrict__ outpre)
{
    extern __shared__ char smc[];
    unsigned short* AH  = (unsigned short*)(smc);
    unsigned short* AL  = (unsigned short*)(smc + SLAB);
    unsigned short* W0H = (unsigned short*)(smc + 2*SLAB);
    unsigned short* W0L = (unsigned short*)(smc + 3*SLAB);
    unsigned short* W1H = (unsigned short*)(smc + 4*SLAB);
    unsigned short* W1L = (unsigned short*)(smc + 5*SLAB);
    int*   nid = (int*)(smc + 6*SLAB);
    float* rel = (float*)(smc + 6*SLAB + 512);

    int tid = threadIdx.x;
    int lane = tid & 31, wid = tid >> 5;
    int gid = lane >> 2, tig = lane & 3;
    int wm = wid & 3, wn = wid >> 2;
    int p0 = blockIdx.x * 8;

    if (tid < 128) {
        int r = tid;
        int p = p0 + (r >> 4);
        int g = g_idx[(size_t)p*NK + (r & 15)];
        nid[r] = g;
        rel[r*3+0] = xyz[(size_t)g*3+0] - xyz[(size_t)p*3+0];
        rel[r*3+1] = xyz[(size_t)g*3+1] - xyz[(size_t)p*3+1];
        rel[r*3+2] = xyz[(size_t)g*3+2] - xyz[(size_t)p*3+2];
    }
    __syncthreads();

    {   // u = relu(pW1'*rel + b1'), split to bf16 hi/lo slabs
        int c = tid & 127;
        int r0 = tid >> 7;
        float w0 = g_pW1s[c*3+0], w1 = g_pW1s[c*3+1], w2 = g_pW1s[c*3+2];
        float bb = g_b1p[c];
        #pragma unroll
        for (int r = r0; r < 128; r += 4) {
            float v = fmaf(w0, rel[r*3+0], fmaf(w1, rel[r*3+1], fmaf(w2, rel[r*3+2], bb)));
            v = fmaxf(v, 0.f);
            __nv_bfloat16 bh = __float2bfloat16_rn(v);
            AH[r*WSH + c] = __bfloat16_as_ushort(bh);
            AL[r*WSH + c] = __bfloat16_as_ushort(__float2bfloat16_rn(v - __bfloat162float(bh)));
        }
    }

    stage_w(g_W3hi,  W0H, tid);
    stage_w(g_W3lo,  W0L, tid);
    stage_w(g_pW2hi, W1H, tid);
    stage_w(g_pW2lo, W1L, tid);
    __syncthreads();

    float acc1[2][4][4], acc2[2][4][4];
    #pragma unroll
    for (int mt = 0; mt < 2; ++mt)
        #pragma unroll
        for (int nt = 0; nt < 4; ++nt)
            #pragma unroll
            for (int j = 0; j < 4; ++j) { acc1[mt][nt][j] = 0.f; acc2[mt][nt][j] = 0.f; }

    // fused GEMM1a (W3') + GEMM1b (pW2), shared A = u
    #pragma unroll
    for (int kc = 0; kc < 8; ++kc) {
        unsigned ah[2][4], al[2][4];
        #pragma unroll
        for (int mt = 0; mt < 2; ++mt) {
            int r = wm*32 + mt*16 + gid;
            int ao = r*WSH + kc*16 + 2*tig;
            ah[mt][0] = *(const unsigned*)(AH + ao);
            ah[mt][1] = *(const unsigned*)(AH + ao + 8*WSH);
            ah[mt][2] = *(const unsigned*)(AH + ao + 8);
            ah[mt][3] = *(const unsigned*)(AH + ao + 8*WSH + 8);
            al[mt][0] = *(const unsigned*)(AL + ao);
            al[mt][1] = *(const unsigned*)(AL + ao + 8*WSH);
            al[mt][2] = *(const unsigned*)(AL + ao + 8);
            al[mt][3] = *(const unsigned*)(AL + ao + 8*WSH + 8);
        }
        #pragma unroll
        for (int nt = 0; nt < 4; ++nt) {
            int o = wn*32 + nt*8 + gid;
            int bo = o*WSH + kc*16 + 2*tig;
            unsigned w3h0 = *(const unsigned*)(W0H + bo);
            unsigned w3h1 = *(const unsigned*)(W0H + bo + 8);
            unsigned w3l0 = *(const unsigned*)(W0L + bo);
            unsigned w3l1 = *(const unsigned*)(W0L + bo + 8);
            unsigned p2h0 = *(const unsigned*)(W1H + bo);
            unsigned p2h1 = *(const unsigned*)(W1H + bo + 8);
            unsigned p2l0 = *(const unsigned*)(W1L + bo);
            unsigned p2l1 = *(const unsigned*)(W1L + bo + 8);
            #pragma unroll
            for (int mt = 0; mt < 2; ++mt) {
                mma16(acc1[mt][nt], ah[mt], w3h0, w3h1);
                mma16(acc1[mt][nt], ah[mt], w3l0, w3l1);
                mma16(acc1[mt][nt], al[mt], w3h0, w3h1);
                mma16(acc2[mt][nt], ah[mt], p2h0, p2h1);
                mma16(acc2[mt][nt], ah[mt], p2l0, p2l1);
                mma16(acc2[mt][nt], al[mt], p2h0, p2h1);
            }
        }
    }
    __syncthreads();

    // epilogue 1: h = relu(acc1 + t1[p] - t2[g] + cc) -> AH/AL
    #pragma unroll
    for (int mt = 0; mt < 2; ++mt) {
        int rL = wm*32 + mt*16 + gid;
        int p = p0 + wm*2 + mt;
        int g0 = nid[rL], g1 = nid[rL+8];
        #pragma unroll
        for (int nt = 0; nt < 4; ++nt) {
            int c = wn*32 + nt*8 + 2*tig;
            float2 t1v = *(const float2*)(g_t1 + (size_t)p*NC + c);
            float2 ccv = *(const float2*)(g_cc + c);
            float2 t20 = *(const float2*)(g_t2 + (size_t)g0*NC + c);
            float2 t21 = *(const float2*)(g_t2 + (size_t)g1*NC + c);
            float h00 = fmaxf(acc1[mt][nt][0] + t1v.x - t20.x + ccv.x, 0.f);
            float h01 = fmaxf(acc1[mt][nt][1] + t1v.y - t20.y + ccv.y, 0.f);
            float h10 = fmaxf(acc1[mt][nt][2] + t1v.x - t21.x + ccv.x, 0.f);
            float h11 = fmaxf(acc1[mt][nt][3] + t1v.y - t21.y + ccv.y, 0.f);
            unsigned hi, lo;
            split2(h00, h01, hi, lo);
            *(unsigned*)(AH + rL*WSH + c) = hi;
            *(unsigned*)(AL + rL*WSH + c) = lo;
            split2(h10, h11, hi, lo);
            *(unsigned*)(AH + (rL+8)*WSH + c) = hi;
            *(unsigned*)(AL + (rL+8)*WSH + c) = lo;
        }
    }

    // epilogue 2: pvr = acc2 + pb2 + vf[g]
    float pvr[2][4][4];
    #pragma unroll
    for (int mt = 0; mt < 2; ++mt) {
        int rL = wm*32 + mt*16 + gid;
        int g0 = nid[rL], g1 = nid[rL+8];
        #pragma unroll
        for (int nt = 0; nt < 4; ++nt) {
            int c = wn*32 + nt*8 + 2*tig;
            float2 pbv = *(const float2*)(pb2 + c);
            float2 v0 = *(const float2*)(g_vf + (size_t)g0*NC + c);
            float2 v1 = *(const float2*)(g_vf + (size_t)g1*NC + c);
            pvr[mt][nt][0] = acc2[mt][nt][0] + pbv.x + v0.x;
            pvr[mt][nt][1] = acc2[mt][nt][1] + pbv.y + v0.y;
            pvr[mt][nt][2] = acc2[mt][nt][2] + pbv.x + v1.x;
            pvr[mt][nt][3] = acc2[mt][nt][3] + pbv.y + v1.y;
        }
    }

    stage_w(g_aW2hi, W0H, tid);
    stage_w(g_aW2lo, W0L, tid);
    __syncthreads();

    // GEMM2: logits = h @ aW2^T  (ab2 cancels in softmax)
    #pragma unroll
    for (int mt = 0; mt < 2; ++mt)
        #pragma unroll
        for (int nt = 0; nt < 4; ++nt)
            #pragma unroll
            for (int j = 0; j < 4; ++j) acc1[mt][nt][j] = 0.f;

    #pragma unroll
    for (int kc = 0; kc < 8; ++kc) {
        unsigned ah[2][4], al[2][4];
        #pragma unroll
        for (int mt = 0; mt < 2; ++mt) {
            int r = wm*32 + mt*16 + gid;
            int ao = r*WSH + kc*16 + 2*tig;
            ah[mt][0] = *(const unsigned*)(AH + ao);
            ah[mt][1] = *(const unsigned*)(AH + ao + 8*WSH);
            ah[mt][2] = *(const unsigned*)(AH + ao + 8);
            ah[mt][3] = *(const unsigned*)(AH + ao + 8*WSH + 8);
            al[mt][0] = *(const unsigned*)(AL + ao);
            al[mt][1] = *(const unsigned*)(AL + ao + 8*WSH);
            al[mt][2] = *(const unsigned*)(AL + ao + 8);
            al[mt][3] = *(const unsigned*)(AL + ao + 8*WSH + 8);
        }
        #pragma unroll
        for (int nt = 0; nt < 4; ++nt) {
            int o = wn*32 + nt*8 + gid;
            int bo = o*WSH + kc*16 + 2*tig;
            unsigned bh0 = *(const unsigned*)(W0H + bo);
            unsigned bh1 = *(const unsigned*)(W0H + bo + 8);
            unsigned bl0 = *(const unsigned*)(W0L + bo);
            unsigned bl1 = *(const unsigned*)(W0L + bo + 8);
            #pragma unroll
            for (int mt = 0; mt < 2; ++mt) {
                mma16(acc1[mt][nt], ah[mt], bh0, bh1);
                mma16(acc1[mt][nt], ah[mt], bl0, bl1);
                mma16(acc1[mt][nt], al[mt], bh0, bh1);
            }
        }
    }

    // softmax over K + weighted reduce, in registers
    #pragma unroll
    for (int mt = 0; mt < 2; ++mt) {
        int p = p0 + wm*2 + mt;
        #pragma unroll
        for (int nt = 0; nt < 4; ++nt) {
            #pragma unroll
            for (int j = 0; j < 2; ++j) {
                float x0 = acc1[mt][nt][j], x1 = acc1[mt][nt][2+j];
                float m = fmaxf(x0, x1);
                m = fmaxf(m, __shfl_xor_sync(0xffffffffu, m, 4));
                m = fmaxf(m, __shfl_xor_sync(0xffffffffu, m, 8));
                m = fmaxf(m, __shfl_xor_sync(0xffffffffu, m, 16));
                float e0 = __expf(x0 - m), e1 = __expf(x1 - m);
                float s = e0 + e1;
                float a = fmaf(e0, pvr[mt][nt][j], e1 * pvr[mt][nt][2+j]);
                s += __shfl_xor_sync(0xffffffffu, s, 4);
                a += __shfl_xor_sync(0xffffffffu, a, 4);
                s += __shfl_xor_sync(0xffffffffu, s, 8);
                a += __shfl_xor_sync(0xffffffffu, a, 8);
                s += __shfl_xor_sync(0xffffffffu, s, 16);
                a += __shfl_xor_sync(0xffffffffu, a, 16);
                if (gid == 0)
                    outpre[(size_t)p*NC + wn*32 + nt*8 + 2*tig + j] = a / s;
            }
        }
    }
}

// ---------------- final GEMM (Wout, scalar) ----------------
__global__ __launch_bounds__(256) void gemm_rt(
    const float* __restrict__ A, const float* __restrict__ Wt, float* __restrict__ out)
{
    extern __shared__ float sm[];
    float* AS  = sm;
    float* WTs = AS + NC*SA;

    int tid = threadIdx.x, tx = tid & 15, ty = tid >> 4;
    int p0 = blockIdx.x * 128;

    #pragma unroll
    for (int it = 0; it < 16; ++it) {
        int e = (it*256 + tid) * 4;
        int r = e >> 7, c = e & 127;
        *(float4*)(AS + r*SA + c) = *(const float4*)(A + (size_t)(p0 + r)*NC + c);
    }

    float acc[8][8];
    #pragma unroll
    for (int ir = 0; ir < 8; ++ir)
        #pragma unroll
        for (int io = 0; io < 8; ++io) acc[ir][io] = 0.f;

    #pragma unroll 1
    for (int k0 = 0; k0 < NC; k0 += 16) {
        __syncthreads();
        int e = tid * 8;
        *(float4*)(WTs + e)     = *(const float4*)(Wt + k0*NC + e);
        *(float4*)(WTs + e + 4) = *(const float4*)(Wt + k0*NC + e + 4);
        __syncthreads();
        #pragma unroll
        for (int kk = 0; kk < 16; ++kk) {
            float wf[8];
            ((float4*)wf)[0] = *(const float4*)(WTs + kk*NC + tx*8);
            ((float4*)wf)[1] = *(const float4*)(WTs + kk*NC + tx*8 + 4);
            float af[8];
            #pragma unroll
            for (int ir = 0; ir < 8; ++ir) af[ir] = AS[(ty*8 + ir)*SA + k0 + kk];
            #pragma unroll
            for (int ir = 0; ir < 8; ++ir)
                #pragma unroll
                for (int io = 0; io < 8; ++io)
                    acc[ir][io] = fmaf(af[ir], wf[io], acc[ir][io]);
        }
    }

    #pragma unroll
    for (int ir = 0; ir < 8; ++ir) {
        int r = p0 + ty*8 + ir;
        #pragma unroll
        for (int io4 = 0; io4 < 8; io4 += 4) {
            float4 v;
            v.x = acc[ir][io4+0]; v.y = acc[ir][io4+1];
            v.z = acc[ir][io4+2]; v.w = acc[ir][io4+3];
            *(float4*)(out + (size_t)r*NC + tx*8 + io4) = v;
        }
    }
}

// ---------------- launch ----------------
#define GEMM_SMEM  ((NC*SA + 16*NC) * 4)
#define G3_SMEM    (6*SLAB)
#define MAIN_SMEM  (6*SLAB + 512 + NC*3*4)

extern "C" void kernel_launch(void* const* d_in, const int* in_sizes, int n_in,
                              void* d_out, int out_size)
{
    const float* xyz   = (const float*)d_in[0];
    const float* feat  = (const float*)d_in[1];
    const float* Wq    = (const float*)d_in[2];
    const float* Wk    = (const float*)d_in[3];
    const float* Wv    = (const float*)d_in[4];
    const float* pW1   = (const float*)d_in[5];
    const float* pb1   = (const float*)d_in[6];
    const float* pg    = (const float*)d_in[7];
    const float* pbeta = (const float*)d_in[8];
    const float* pmean = (const float*)d_in[9];
    const float* pvar  = (const float*)d_in[10];
    const float* pW2   = (const float*)d_in[11];
    const float* pb2   = (const float*)d_in[12];
    const float* aW1   = (const float*)d_in[13];
    const float* ab1   = (const float*)d_in[14];
    const float* ag    = (const float*)d_in[15];
    const float* abeta = (const float*)d_in[16];
    const float* amean = (const float*)d_in[17];
    const float* avar  = (const float*)d_in[18];
    const float* aW2   = (const float*)d_in[19];
    const float* ab2   = (const float*)d_in[20];  (void)ab2;
    const float* Wout  = (const float*)d_in[21];
    float* out = (float*)d_out;

    void *p_t1, *p_t2, *p_vf, *p_outpre, *p_idx, *p_pd, *p_pi, *p_Woutt;
    cudaGetSymbolAddress(&p_t1, g_t1);
    cudaGetSymbolAddress(&p_t2, g_t2);
    cudaGetSymbolAddress(&p_vf, g_vf);
    cudaGetSymbolAddress(&p_outpre, g_outpre);
    cudaGetSymbolAddress(&p_idx, g_idx);
    cudaGetSymbolAddress(&p_pd, g_pd);
    cudaGetSymbolAddress(&p_pi, g_pi);
    cudaGetSymbolAddress(&p_Woutt, g_Woutt);

    cudaFuncSetAttribute(gemm_rt,    cudaFuncAttributeMaxDynamicSharedMemorySize, GEMM_SMEM);
    cudaFuncSetAttribute(gemm3_tc,   cudaFuncAttributeMaxDynamicSharedMemorySize, G3_SMEM);
    cudaFuncSetAttribute(fused_main, cudaFuncAttributeMaxDynamicSharedMemorySize, MAIN_SMEM);

    setup_kernel<<<NC, NC>>>(Wq, Wk, Wv, pW1, pb1, pg, pbeta, pmean, pvar,
                             pW2, pb2, aW1, ab1, ag, abeta, amean, avar, aW2, Wout);

    knn_part<<<dim3(NP/256, KSPLIT), 128>>>(xyz, (float*)p_pd, (int*)p_pi);
    knn_merge<<<NP/128, 128>>>((const float*)p_pd, (const int*)p_pi, (int*)p_idx);

    gemm3_tc<<<NP/128, 512, G3_SMEM>>>(feat, (float*)p_t1, (float*)p_t2, (float*)p_vf);

    fused_main<<<NP/8, 512, MAIN_SMEM>>>(xyz, pb2, (float*)p_outpre);

    gemm_rt<<<NP/128, 256, GEMM_SMEM>>>((const float*)p_outpre, (const float*)p_Woutt, out);
}

// round 15
// speedup vs baseline: 3.3551x; 1.0467x over previous
#include <cuda_runtime.h>
#include <cuda_bf16.h>
#include <math.h>
#include <stdint.h>

#define NB 2
#define NN 8192
#define NC 128
#define NK 16
#define NP (NB*NN)
#define EPSF 1e-5f
#define SA 132
#define WSH 136              // packed-slab row stride in ushorts (128 + 8 pad)
#define SLAB (NC*WSH*2)      // slab bytes = 34816
#define KSPLIT 8
#define KCH (NN/KSPLIT)      // 1024 candidates per chunk

__device__ float g_t1[NP*NC];
__device__ float g_t2[NP*NC];
__device__ float g_vf[NP*NC];
__device__ float g_outpre[NP*NC];
__device__ int   g_idx[NP*NK];
__device__ float g_pd[NP*KSPLIT*NK];
__device__ int   g_pi[NP*KSPLIT*NK];

__device__ float g_Woutt[NC*NC];
__device__ float g_cc[NC];
__device__ float g_pW1s[NC*3];
__device__ float g_b1p[NC];

// bf16 hi/lo weight splits, [o][k] row-major ushorts
__device__ unsigned short g_Athi[NC*NC], g_Atlo[NC*NC];
__device__ unsigned short g_Bthi[NC*NC], g_Btlo[NC*NC];
__device__ unsigned short g_Wvhi[NC*NC], g_Wvlo[NC*NC];
__device__ unsigned short g_W3hi[NC*NC],  g_W3lo[NC*NC];
__device__ unsigned short g_pW2hi[NC*NC], g_pW2lo[NC*NC];
__device__ unsigned short g_aW2hi[NC*NC], g_aW2lo[NC*NC];

__device__ __forceinline__ void mma16(float* d, const unsigned* a, unsigned b0, unsigned b1) {
    asm volatile("mma.sync.aligned.m16n8k16.row.col.f32.bf16.bf16.f32 "
        "{%0,%1,%2,%3}, {%4,%5,%6,%7}, {%8,%9}, {%0,%1,%2,%3};"
        : "+f"(d[0]), "+f"(d[1]), "+f"(d[2]), "+f"(d[3])
        : "r"(a[0]), "r"(a[1]), "r"(a[2]), "r"(a[3]), "r"(b0), "r"(b1));
}

// ---- packed f32x2 helpers (sm_100+): two fmaf.rn in one instruction, bit-exact ----
__device__ __forceinline__ unsigned long long pk2(float x) {
    unsigned long long r; asm("mov.b64 %0, {%1, %1};" : "=l"(r) : "f"(x)); return r;
}
__device__ __forceinline__ unsigned long long fma2(unsigned long long a, unsigned long long b,
                                                   unsigned long long c) {
    unsigned long long d;
    asm("fma.rn.f32x2 %0, %1, %2, %3;" : "=l"(d) : "l"(a), "l"(b), "l"(c));
    return d;
}
__device__ __forceinline__ float2 up2(unsigned long long v) {
    float2 f; asm("mov.b64 {%0, %1}, %2;" : "=f"(f.x), "=f"(f.y) : "l"(v)); return f;
}

// split two fp32 into packed bf16x2 hi and lo words (x0 in low half)
__device__ __forceinline__ void split2(float x0, float x1, unsigned& hi, unsigned& lo) {
    __nv_bfloat16 h0 = __float2bfloat16_rn(x0), h1 = __float2bfloat16_rn(x1);
    float r0 = x0 - __bfloat162float(h0);
    float r1 = x1 - __bfloat162float(h1);
    __nv_bfloat16 l0 = __float2bfloat16_rn(r0), l1 = __float2bfloat16_rn(r1);
    hi = ((unsigned)__bfloat16_as_ushort(h1) << 16) | (unsigned)__bfloat16_as_ushort(h0);
    lo = ((unsigned)__bfloat16_as_ushort(l1) << 16) | (unsigned)__bfloat16_as_ushort(l0);
}
__device__ __forceinline__ void splitw(float x, unsigned short* hi, unsigned short* lo, int idx) {
    __nv_bfloat16 b = __float2bfloat16_rn(x);
    hi[idx] = __bfloat16_as_ushort(b);
    lo[idx] = __bfloat16_as_ushort(__float2bfloat16_rn(x - __bfloat162float(b)));
}

// ---------------- setup ----------------
__global__ void setup_kernel(
    const float* __restrict__ Wq, const float* __restrict__ Wk,
    const float* __restrict__ Wv, const float* __restrict__ pW1,
    const float* __restrict__ pb1, const float* __restrict__ pg,
    const float* __restrict__ pbeta, const float* __restrict__ pmean,
    const float* __restrict__ pvar, const float* __restrict__ pW2,
    const float* __restrict__ pb2, const float* __restrict__ aW1,
    const float* __restrict__ ab1, const float* __restrict__ ag,
    const float* __restrict__ abeta, const float* __restrict__ amean,
    const float* __restrict__ avar, const float* __restrict__ aW2,
    const float* __restrict__ Wout)
{
    __shared__ float arow[NC];
    int o = blockIdx.x, i = threadIdx.x;
    arow[i] = aW1[o*NC + i];
    __syncthreads();
    float s2o = ag[o] * rsqrtf(avar[o] + EPSF);
    float sA = 0.f, sB = 0.f, sW = 0.f;
    #pragma unroll 4
    for (int m = 0; m < NC; ++m) {
        float a = arow[m];
        sA = fmaf(a, Wq[m*NC + i], sA);
        sB = fmaf(a, Wk[m*NC + i], sB);
        sW = fmaf(a, pW2[m*NC + i], sW);
    }
    g_Woutt[i*NC + o] = Wout[o*NC + i];

    int e = o*NC + i;
    splitw(s2o * sA, g_Athi, g_Atlo, e);
    splitw(s2o * sB, g_Bthi, g_Btlo, e);
    splitw(Wv[e],    g_Wvhi, g_Wvlo, e);
    splitw(s2o * sW, g_W3hi, g_W3lo, e);
    splitw(pW2[e],   g_pW2hi, g_pW2lo, e);
    splitw(aW2[e],   g_aW2hi, g_aW2lo, e);

    if (o == 0) {
        int c = i;
        float s1 = pg[c] * rsqrtf(pvar[c] + EPSF);
        g_pW1s[c*3+0] = pW1[c*3+0] * s1;
        g_pW1s[c*3+1] = pW1[c*3+1] * s1;
        g_pW1s[c*3+2] = pW1[c*3+2] * s1;
        g_b1p[c] = (pb1[c] - pmean[c]) * s1 + pbeta[c];
        float s2c = ag[c] * rsqrtf(avar[c] + EPSF);
        float c0 = ab1[c];
        for (int m = 0; m < NC; ++m) c0 = fmaf(aW1[c*NC + m], pb2[m], c0);
        g_cc[c] = s2c * c0 + abeta[c] - amean[c] * s2c;
    }
}

// ---------------- KNN stage 1 (scalar, KSPLIT=8, packed f32x2 distances) ----------------
__device__ __forceinline__ void ins16(float d, int m, float bd[NK], int bi[NK]) {
    if (d < bd[NK-1]) {
        bd[NK-1] = d; bi[NK-1] = m;
        #pragma unroll
        for (int s = NK-1; s >= 1; --s) {
            if (bd[s] < bd[s-1]) {
                float td = bd[s]; bd[s] = bd[s-1]; bd[s-1] = td;
                int   ti = bi[s]; bi[s] = bi[s-1]; bi[s-1] = ti;
            }
        }
    }
}

__global__ __launch_bounds__(128) void knn_part(
    const float* __restrict__ xyz, float* __restrict__ pd, int* __restrict__ pi)
{
    __shared__ __align__(16) float cx[256];
    __shared__ __align__(16) float cy[256];
    __shared__ __align__(16) float cz[256];
    __shared__ __align__(16) float cw[256];

    int tid = threadIdx.x;
    int qA = blockIdx.x * 256 + tid;
    int qB = qA + 128;
    int base = (qA / NN) * NN;
    int c0 = base + blockIdx.y * KCH;

    float nax = -2.f*xyz[(size_t)qA*3+0], nay = -2.f*xyz[(size_t)qA*3+1], naz = -2.f*xyz[(size_t)qA*3+2];
    float nbx = -2.f*xyz[(size_t)qB*3+0], nby = -2.f*xyz[(size_t)qB*3+1], nbz = -2.f*xyz[(size_t)qB*3+2];
    unsigned long long pax = pk2(nax), pay = pk2(nay), paz = pk2(naz);
    unsigned long long pbx = pk2(nbx), pby = pk2(nby), pbz = pk2(nbz);

    float bdA[NK], bdB[NK]; int biA[NK], biB[NK];
    #pragma unroll
    for (int k = 0; k < NK; ++k) {
        bdA[k] = INFINITY; biA[k] = 0;
        bdB[k] = INFINITY; biB[k] = 0;
    }

    for (int t0 = 0; t0 < KCH; t0 += 256) {
        __syncthreads();
        #pragma unroll
        for (int j = tid; j < 256; j += 128) {
            int m = c0 + t0 + j;
            float x = xyz[(size_t)m*3+0], y = xyz[(size_t)m*3+1], z = xyz[(size_t)m*3+2];
            cx[j] = x; cy[j] = y; cz[j] = z;
            cw[j] = fmaf(x, x, fmaf(y, y, z*z));
        }
        __syncthreads();
        #pragma unroll 2
        for (int j = 0; j < 256; j += 4) {
            ulonglong2 X = *(const ulonglong2*)(cx + j);
            ulonglong2 Y = *(const ulonglong2*)(cy + j);
            ulonglong2 Z = *(const ulonglong2*)(cz + j);
            ulonglong2 W = *(const ulonglong2*)(cw + j);

            float2 a01 = up2(fma2(pax, X.x, fma2(pay, Y.x, fma2(paz, Z.x, W.x))));
            float2 a23 = up2(fma2(pax, X.y, fma2(pay, Y.y, fma2(paz, Z.y, W.y))));
            if (fminf(fminf(a01.x, a01.y), fminf(a23.x, a23.y)) < bdA[NK-1]) {
                ins16(a01.x, t0+j,   bdA, biA);
                ins16(a01.y, t0+j+1, bdA, biA);
                ins16(a23.x, t0+j+2, bdA, biA);
                ins16(a23.y, t0+j+3, bdA, biA);
            }

            float2 b01 = up2(fma2(pbx, X.x, fma2(pby, Y.x, fma2(pbz, Z.x, W.x))));
            float2 b23 = up2(fma2(pbx, X.y, fma2(pby, Y.y, fma2(pbz, Z.y, W.y))));
            if (fminf(fminf(b01.x, b01.y), fminf(b23.x, b23.y)) < bdB[NK-1]) {
                ins16(b01.x, t0+j,   bdB, biB);
                ins16(b01.y, t0+j+1, bdB, biB);
                ins16(b23.x, t0+j+2, bdB, biB);
                ins16(b23.y, t0+j+3, bdB, biB);
            }
        }
    }
    size_t oA = (size_t)qA*(KSPLIT*NK) + blockIdx.y*NK;
    size_t oB = (size_t)qB*(KSPLIT*NK) + blockIdx.y*NK;
    #pragma unroll
    for (int k = 0; k < NK; ++k) {
        pd[oA+k] = bdA[k]; pi[oA+k] = c0 + biA[k];
        pd[oB+k] = bdB[k]; pi[oB+k] = c0 + biB[k];
    }
}

// ---------------- KNN stage 2: merge ----------------
__global__ __launch_bounds__(128) void knn_merge(
    const float* __restrict__ pd, const int* __restrict__ pi, int* __restrict__ idxo)
{
    int q = blockIdx.x * 128 + threadIdx.x;
    float bd[NK]; int bi[NK];
    #pragma unroll
    for (int k = 0; k < NK; ++k) { bd[k] = INFINITY; bi[k] = 0x7fffffff; }
    size_t ib = (size_t)q * (KSPLIT*NK);
    for (int j = 0; j < KSPLIT*NK; ++j) {
        float d = pd[ib + j];
        int   m = pi[ib + j];
        if (d < bd[NK-1] || (d == bd[NK-1] && m < bi[NK-1])) {
            bd[NK-1] = d; bi[NK-1] = m;
            #pragma unroll
            for (int s = NK-1; s >= 1; --s) {
                bool sw = (bd[s] < bd[s-1]) || (bd[s] == bd[s-1] && bi[s] < bi[s-1]);
                if (sw) {
                    float td = bd[s]; bd[s] = bd[s-1]; bd[s-1] = td;
                    int   ti = bi[s]; bi[s] = bi[s-1]; bi[s-1] = ti;
                }
            }
        }
    }
    #pragma unroll
    for (int k = 0; k < NK; ++k) idxo[(size_t)q*NK + k] = bi[k];
}

// ---------------- stage a 128x128 ushort weight matrix into a smem slab ----------------
__device__ __forceinline__ void stage_w(const unsigned short* __restrict__ g,
                                        unsigned short* s, int tid)
{
    int row = tid >> 2, q = tid & 3;
    #pragma unroll
    for (int j = 0; j < 4; ++j)
        *(uint4*)(s + row*WSH + q*32 + j*8) = *(const uint4*)(g + row*NC + q*32 + j*8);
}

// ---------------- gemm3_tc: t1/t2/vf via bf16x3 tensor cores ----------------
__global__ __launch_bounds__(512, 1) void gemm3_tc(
    const float* __restrict__ feat, float* __restrict__ t1,
    float* __restrict__ t2, float* __restrict__ vf)
{
    extern __shared__ char smc[];
    unsigned short* AH  = (unsigned short*)(smc);
    unsigned short* AL  = (unsigned short*)(smc + SLAB);
    unsigned short* W0H = (unsigned short*)(smc + 2*SLAB);
    unsigned short* W0L = (unsigned short*)(smc + 3*SLAB);
    unsigned short* W1H = (unsigned short*)(smc + 4*SLAB);
    unsigned short* W1L = (unsigned short*)(smc + 5*SLAB);

    int tid = threadIdx.x;
    int lane = tid & 31, wid = tid >> 5;
    int gid = lane >> 2, tig = lane & 3;
    int wm = wid & 3, wn = wid >> 2;
    int p0 = blockIdx.x * 128;

    {
        int row = tid >> 2, q = tid & 3;
        const float* src = feat + (size_t)(p0 + row)*NC + q*32;
        #pragma unroll
        for (int j = 0; j < 32; j += 2) {
            float2 v = *(const float2*)(src + j);
            unsigned hi, lo;
            split2(v.x, v.y, hi, lo);
            *(unsigned*)(AH + row*WSH + q*32 + j) = hi;
            *(unsigned*)(AL + row*WSH + q*32 + j) = lo;
        }
    }
    stage_w(g_Athi, W0H, tid);
    stage_w(g_Atlo, W0L, tid);
    stage_w(g_Bthi, W1H, tid);
    stage_w(g_Btlo, W1L, tid);
    __syncthreads();

    float acc1[2][4][4], acc2[2][4][4];
    #pragma unroll
    for (int mt = 0; mt < 2; ++mt)
        #pragma unroll
        for (int nt = 0; nt < 4; ++nt)
            #pragma unroll
            for (int j = 0; j < 4; ++j) { acc1[mt][nt][j] = 0.f; acc2[mt][nt][j] = 0.f; }

    #pragma unroll
    for (int kc = 0; kc < 8; ++kc) {
        unsigned ah[2][4], al[2][4];
        #pragma unroll
        for (int mt = 0; mt < 2; ++mt) {
            int r = wm*32 + mt*16 + gid;
            int ao = r*WSH + kc*16 + 2*tig;
            ah[mt][0] = *(const unsigned*)(AH + ao);
            ah[mt][1] = *(const unsigned*)(AH + ao + 8*WSH);
            ah[mt][2] = *(const unsigned*)(AH + ao + 8);
            ah[mt][3] = *(const unsigned*)(AH + ao + 8*WSH + 8);
            al[mt][0] = *(const unsigned*)(AL + ao);
            al[mt][1] = *(const unsigned*)(AL + ao + 8*WSH);
            al[mt][2] = *(const unsigned*)(AL + ao + 8);
            al[mt][3] = *(const unsigned*)(AL + ao + 8*WSH + 8);
        }
        #pragma unroll
        for (int nt = 0; nt < 4; ++nt) {
            int o = wn*32 + nt*8 + gid;
            int bo = o*WSH + kc*16 + 2*tig;
            unsigned a_h0 = *(const unsigned*)(W0H + bo);
            unsigned a_h1 = *(const unsigned*)(W0H + bo + 8);
            unsigned a_l0 = *(const unsigned*)(W0L + bo);
            unsigned a_l1 = *(const unsigned*)(W0L + bo + 8);
            unsigned b_h0 = *(const unsigned*)(W1H + bo);
            unsigned b_h1 = *(const unsigned*)(W1H + bo + 8);
            unsigned b_l0 = *(const unsigned*)(W1L + bo);
            unsigned b_l1 = *(const unsigned*)(W1L + bo + 8);
            #pragma unroll
            for (int mt = 0; mt < 2; ++mt) {
                mma16(acc1[mt][nt], ah[mt], a_h0, a_h1);
                mma16(acc1[mt][nt], ah[mt], a_l0, a_l1);
                mma16(acc1[mt][nt], al[mt], a_h0, a_h1);
                mma16(acc2[mt][nt], ah[mt], b_h0, b_h1);
                mma16(acc2[mt][nt], ah[mt], b_l0, b_l1);
                mma16(acc2[mt][nt], al[mt], b_h0, b_h1);
            }
        }
    }

    #pragma unroll
    for (int mt = 0; mt < 2; ++mt) {
        int rL = p0 + wm*32 + mt*16 + gid;
        #pragma unroll
        for (int nt = 0; nt < 4; ++nt) {
            int c = wn*32 + nt*8 + 2*tig;
            *(float2*)(t1 + (size_t)rL*NC + c)     = make_float2(acc1[mt][nt][0], acc1[mt][nt][1]);
            *(float2*)(t1 + (size_t)(rL+8)*NC + c) = make_float2(acc1[mt][nt][2], acc1[mt][nt][3]);
            *(float2*)(t2 + (size_t)rL*NC + c)     = make_float2(acc2[mt][nt][0], acc2[mt][nt][1]);
            *(float2*)(t2 + (size_t)(rL+8)*NC + c) = make_float2(acc2[mt][nt][2], acc2[mt][nt][3]);
        }
    }

    __syncthreads();
    stage_w(g_Wvhi, W0H, tid);
    stage_w(g_Wvlo, W0L, tid);
    __syncthreads();

    #pragma unroll
    for (int mt = 0; mt < 2; ++mt)
        #pragma unroll
        for (int nt = 0; nt < 4; ++nt)
            #pragma unroll
            for (int j = 0; j < 4; ++j) acc1[mt][nt][j] = 0.f;

    #pragma unroll
    for (int kc = 0; kc < 8; ++kc) {
        unsigned ah[2][4], al[2][4];
        #pragma unroll
        for (int mt = 0; mt < 2; ++mt) {
            int r = wm*32 + mt*16 + gid;
            int ao = r*WSH + kc*16 + 2*tig;
            ah[mt][0] = *(const unsigned*)(AH + ao);
            ah[mt][1] = *(const unsigned*)(AH + ao + 8*WSH);
            ah[mt][2] = *(const unsigned*)(AH + ao + 8);
            ah[mt][3] = *(const unsigned*)(AH + ao + 8*WSH + 8);
            al[mt][0] = *(const unsigned*)(AL + ao);
            al[mt][1] = *(const unsigned*)(AL + ao + 8*WSH);
            al[mt][2] = *(const unsigned*)(AL + ao + 8);
            al[mt][3] = *(const unsigned*)(AL + ao + 8*WSH + 8);
        }
        #pragma unroll
        for (int nt = 0; nt < 4; ++nt) {
            int o = wn*32 + nt*8 + gid;
            int bo = o*WSH + kc*16 + 2*tig;
            unsigned bh0 = *(const unsigned*)(W0H + bo);
            unsigned bh1 = *(const unsigned*)(W0H + bo + 8);
            unsigned bl0 = *(const unsigned*)(W0L + bo);
            unsigned bl1 = *(const unsigned*)(W0L + bo + 8);
            #pragma unroll
            for (int mt = 0; mt < 2; ++mt) {
                mma16(acc1[mt][nt], ah[mt], bh0, bh1);
                mma16(acc1[mt][nt], ah[mt], bl0, bl1);
                mma16(acc1[mt][nt], al[mt], bh0, bh1);
            }
        }
    }
    #pragma unroll
    for (int mt = 0; mt < 2; ++mt) {
        int rL = p0 + wm*32 + mt*16 + gid;
        #pragma unroll
        for (int nt = 0; nt < 4; ++nt) {
            int c = wn*32 + nt*8 + 2*tig;
            *(float2*)(vf + (size_t)rL*NC + c)     = make_float2(acc1[mt][nt][0], acc1[mt][nt][1]);
            *(float2*)(vf + (size_t)(rL+8)*NC + c) = make_float2(acc1[mt][nt][2], acc1[mt][nt][3]);
        }
    }
}

// ---------------- fused_main: bf16x3 m16n8k16 tensor cores ----------------
__global__ __launch_bounds__(512, 1) void fused_main(
    const float* __restrict__ xyz, const float* __restrict__ pb2,
    float* __restrict__ outpre)
{
    extern __shared__ char smc[];
    unsigned short* AH  = (unsigned short*)(smc);
    unsigned short* AL  = (unsigned short*)(smc + SLAB);
    unsigned short* W0H = (unsigned short*)(smc + 2*SLAB);
    unsigned short* W0L = (unsigned short*)(smc + 3*SLAB);
    unsigned short* W1H = (unsigned short*)(smc + 4*SLAB);
    unsigned short* W1L = (unsigned short*)(smc + 5*SLAB);
    int*   nid = (int*)(smc + 6*SLAB);
    float* rel = (float*)(smc + 6*SLAB + 512);

    int tid = threadIdx.x;
    int lane = tid & 31, wid = tid >> 5;
    int gid = lane >> 2, tig = lane & 3;
    int wm = wid & 3, wn = wid >> 2;
    int p0 = blockIdx.x * 8;

    if (tid < 128) {
        int r = tid;
        int p = p0 + (r >> 4);
        int g = g_idx[(size_t)p*NK + (r & 15)];
        nid[r] = g;
        rel[r*3+0] = xyz[(size_t)g*3+0] - xyz[(size_t)p*3+0];
        rel[r*3+1] = xyz[(size_t)g*3+1] - xyz[(size_t)p*3+1];
        rel[r*3+2] = xyz[(size_t)g*3+2] - xyz[(size_t)p*3+2];
    }
    __syncthreads();

    {   // u = relu(pW1'*rel + b1'), split to bf16 hi/lo slabs
        int c = tid & 127;
        int r0 = tid >> 7;
        float w0 = g_pW1s[c*3+0], w1 = g_pW1s[c*3+1], w2 = g_pW1s[c*3+2];
        float bb = g_b1p[c];
        #pragma unroll
        for (int r = r0; r < 128; r += 4) {
            float v = fmaf(w0, rel[r*3+0], fmaf(w1, rel[r*3+1], fmaf(w2, rel[r*3+2], bb)));
            v = fmaxf(v, 0.f);
            __nv_bfloat16 bh = __float2bfloat16_rn(v);
            AH[r*WSH + c] = __bfloat16_as_ushort(bh);
            AL[r*WSH + c] = __bfloat16_as_ushort(__float2bfloat16_rn(v - __bfloat162float(bh)));
        }
    }

    stage_w(g_W3hi,  W0H, tid);
    stage_w(g_W3lo,  W0L, tid);
    stage_w(g_pW2hi, W1H, tid);
    stage_w(g_pW2lo, W1L, tid);
    __syncthreads();

    float acc1[2][4][4], acc2[2][4][4];
    #pragma unroll
    for (int mt = 0; mt < 2; ++mt)
        #pragma unroll
        for (int nt = 0; nt < 4; ++nt)
            #pragma unroll
            for (int j = 0; j < 4; ++j) { acc1[mt][nt][j] = 0.f; acc2[mt][nt][j] = 0.f; }

    // fused GEMM1a (W3') + GEMM1b (pW2), shared A = u
    #pragma unroll
    for (int kc = 0; kc < 8; ++kc) {
        unsigned ah[2][4], al[2][4];
        #pragma unroll
        for (int mt = 0; mt < 2; ++mt) {
            int r = wm*32 + mt*16 + gid;
            int ao = r*WSH + kc*16 + 2*tig;
            ah[mt][0] = *(const unsigned*)(AH + ao);
            ah[mt][1] = *(const unsigned*)(AH + ao + 8*WSH);
            ah[mt][2] = *(const unsigned*)(AH + ao + 8);
            ah[mt][3] = *(const unsigned*)(AH + ao + 8*WSH + 8);
            al[mt][0] = *(const unsigned*)(AL + ao);
            al[mt][1] = *(const unsigned*)(AL + ao + 8*WSH);
            al[mt][2] = *(const unsigned*)(AL + ao + 8);
            al[mt][3] = *(const unsigned*)(AL + ao + 8*WSH + 8);
        }
        #pragma unroll
        for (int nt = 0; nt < 4; ++nt) {
            int o = wn*32 + nt*8 + gid;
            int bo = o*WSH + kc*16 + 2*tig;
            unsigned w3h0 = *(const unsigned*)(W0H + bo);
            unsigned w3h1 = *(const unsigned*)(W0H + bo + 8);
            unsigned w3l0 = *(const unsigned*)(W0L + bo);
            unsigned w3l1 = *(const unsigned*)(W0L + bo + 8);
            unsigned p2h0 = *(const unsigned*)(W1H + bo);
            unsigned p2h1 = *(const unsigned*)(W1H + bo + 8);
            unsigned p2l0 = *(const unsigned*)(W1L + bo);
            unsigned p2l1 = *(const unsigned*)(W1L + bo + 8);
            #pragma unroll
            for (int mt = 0; mt < 2; ++mt) {
                mma16(acc1[mt][nt], ah[mt], w3h0, w3h1);
                mma16(acc1[mt][nt], ah[mt], w3l0, w3l1);
                mma16(acc1[mt][nt], al[mt], w3h0, w3h1);
                mma16(acc2[mt][nt], ah[mt], p2h0, p2h1);
                mma16(acc2[mt][nt], ah[mt], p2l0, p2l1);
                mma16(acc2[mt][nt], al[mt], p2h0, p2h1);
            }
        }
    }
    __syncthreads();

    // epilogue 1: h = relu(acc1 + t1[p] - t2[g] + cc) -> AH/AL
    #pragma unroll
    for (int mt = 0; mt < 2; ++mt) {
        int rL = wm*32 + mt*16 + gid;
        int p = p0 + wm*2 + mt;
        int g0 = nid[rL], g1 = nid[rL+8];
        #pragma unroll
        for (int nt = 0; nt < 4; ++nt) {
            int c = wn*32 + nt*8 + 2*tig;
            float2 t1v = *(const float2*)(g_t1 + (size_t)p*NC + c);
            float2 ccv = *(const float2*)(g_cc + c);
            float2 t20 = *(const float2*)(g_t2 + (size_t)g0*NC + c);
            float2 t21 = *(const float2*)(g_t2 + (size_t)g1*NC + c);
            float h00 = fmaxf(acc1[mt][nt][0] + t1v.x - t20.x + ccv.x, 0.f);
            float h01 = fmaxf(acc1[mt][nt][1] + t1v.y - t20.y + ccv.y, 0.f);
            float h10 = fmaxf(acc1[mt][nt][2] + t1v.x - t21.x + ccv.x, 0.f);
            float h11 = fmaxf(acc1[mt][nt][3] + t1v.y - t21.y + ccv.y, 0.f);
            unsigned hi, lo;
            split2(h00, h01, hi, lo);
            *(unsigned*)(AH + rL*WSH + c) = hi;
            *(unsigned*)(AL + rL*WSH + c) = lo;
            split2(h10, h11, hi, lo);
            *(unsigned*)(AH + (rL+8)*WSH + c) = hi;
            *(unsigned*)(AL + (rL+8)*WSH + c) = lo;
        }
    }

    // epilogue 2: pvr = acc2 + pb2 + vf[g]
    float pvr[2][4][4];
    #pragma unroll
    for (int mt = 0; mt < 2; ++mt) {
        int rL = wm*32 + mt*16 + gid;
        int g0 = nid[rL], g1 = nid[rL+8];
        #pragma unroll
        for (int nt = 0; nt < 4; ++nt) {
            int c = wn*32 + nt*8 + 2*tig;
            float2 pbv = *(const float2*)(pb2 + c);
            float2 v0 = *(const float2*)(g_vf + (size_t)g0*NC + c);
            float2 v1 = *(const float2*)(g_vf + (size_t)g1*NC + c);
            pvr[mt][nt][0] = acc2[mt][nt][0] + pbv.x + v0.x;
            pvr[mt][nt][1] = acc2[mt][nt][1] + pbv.y + v0.y;
            pvr[mt][nt][2] = acc2[mt][nt][2] + pbv.x + v1.x;
            pvr[mt][nt][3] = acc2[mt][nt][3] + pbv.y + v1.y;
        }
    }

    stage_w(g_aW2hi, W0H, tid);
    stage_w(g_aW2lo, W0L, tid);
    __syncthreads();

    // GEMM2: logits = h @ aW2^T  (ab2 cancels in softmax)
    #pragma unroll
    for (int mt = 0; mt < 2; ++mt)
        #pragma unroll
        for (int nt = 0; nt < 4; ++nt)
            #pragma unroll
            for (int j = 0; j < 4; ++j) acc1[mt][nt][j] = 0.f;

    #pragma unroll
    for (int kc = 0; kc < 8; ++kc) {
        unsigned ah[2][4], al[2][4];
        #pragma unroll
        for (int mt = 0; mt < 2; ++mt) {
            int r = wm*32 + mt*16 + gid;
            int ao = r*WSH + kc*16 + 2*tig;
            ah[mt][0] = *(const unsigned*)(AH + ao);
            ah[mt][1] = *(const unsigned*)(AH + ao + 8*WSH);
            ah[mt][2] = *(const unsigned*)(AH + ao + 8);
            ah[mt][3] = *(const unsigned*)(AH + ao + 8*WSH + 8);
            al[mt][0] = *(const unsigned*)(AL + ao);
            al[mt][1] = *(const unsigned*)(AL + ao + 8*WSH);
            al[mt][2] = *(const unsigned*)(AL + ao + 8);
            al[mt][3] = *(const unsigned*)(AL + ao + 8*WSH + 8);
        }
        #pragma unroll
        for (int nt = 0; nt < 4; ++nt) {
            int o = wn*32 + nt*8 + gid;
            int bo = o*WSH + kc*16 + 2*tig;
            unsigned bh0 = *(const unsigned*)(W0H + bo);
            unsigned bh1 = *(const unsigned*)(W0H + bo + 8);
            unsigned bl0 = *(const unsigned*)(W0L + bo);
            unsigned bl1 = *(const unsigned*)(W0L + bo + 8);
            #pragma unroll
            for (int mt = 0; mt < 2; ++mt) {
                mma16(acc1[mt][nt], ah[mt], bh0, bh1);
                mma16(acc1[mt][nt], ah[mt], bl0, bl1);
                mma16(acc1[mt][nt], al[mt], bh0, bh1);
            }
        }
    }

    // softmax over K + weighted reduce, in registers
    #pragma unroll
    for (int mt = 0; mt < 2; ++mt) {
        int p = p0 + wm*2 + mt;
        #pragma unroll
        for (int nt = 0; nt < 4; ++nt) {
            #pragma unroll
            for (int j = 0; j < 2; ++j) {
                float x0 = acc1[mt][nt][j], x1 = acc1[mt][nt][2+j];
                float m = fmaxf(x0, x1);
                m = fmaxf(m, __shfl_xor_sync(0xffffffffu, m, 4));
                m = fmaxf(m, __shfl_xor_sync(0xffffffffu, m, 8));
                m = fmaxf(m, __shfl_xor_sync(0xffffffffu, m, 16));
                float e0 = __expf(x0 - m), e1 = __expf(x1 - m);
                float s = e0 + e1;
                float a = fmaf(e0, pvr[mt][nt][j], e1 * pvr[mt][nt][2+j]);
                s += __shfl_xor_sync(0xffffffffu, s, 4);
                a += __shfl_xor_sync(0xffffffffu, a, 4);
                s += __shfl_xor_sync(0xffffffffu, s, 8);
                a += __shfl_xor_sync(0xffffffffu, a, 8);
                s += __shfl_xor_sync(0xffffffffu, s, 16);
                a += __shfl_xor_sync(0xffffffffu, a, 16);
                if (gid == 0)
                    outpre[(size_t)p*NC + wn*32 + nt*8 + 2*tig + j] = a / s;
            }
        }
    }
}

// ---------------- final GEMM (Wout, scalar) ----------------
__global__ __launch_bounds__(256) void gemm_rt(
    const float* __restrict__ A, const float* __restrict__ Wt, float* __restrict__ out)
{
    extern __shared__ float sm[];
    float* AS  = sm;
    float* WTs = AS + NC*SA;

    int tid = threadIdx.x, tx = tid & 15, ty = tid >> 4;
    int p0 = blockIdx.x * 128;

    #pragma unroll
    for (int it = 0; it < 16; ++it) {
        int e = (it*256 + tid) * 4;
        int r = e >> 7, c = e & 127;
        *(float4*)(AS + r*SA + c) = *(const float4*)(A + (size_t)(p0 + r)*NC + c);
    }

    float acc[8][8];
    #pragma unroll
    for (int ir = 0; ir < 8; ++ir)
        #pragma unroll
        for (int io = 0; io < 8; ++io) acc[ir][io] = 0.f;

    #pragma unroll 1
    for (int k0 = 0; k0 < NC; k0 += 16) {
        __syncthreads();
        int e = tid * 8;
        *(float4*)(WTs + e)     = *(const float4*)(Wt + k0*NC + e);
        *(float4*)(WTs + e + 4) = *(const float4*)(Wt + k0*NC + e + 4);
        __syncthreads();
        #pragma unroll
        for (int kk = 0; kk < 16; ++kk) {
            float wf[8];
            ((float4*)wf)[0] = *(const float4*)(WTs + kk*NC + tx*8);
            ((float4*)wf)[1] = *(const float4*)(WTs + kk*NC + tx*8 + 4);
            float af[8];
            #pragma unroll
            for (int ir = 0; ir < 8; ++ir) af[ir] = AS[(ty*8 + ir)*SA + k0 + kk];
            #pragma unroll
            for (int ir = 0; ir < 8; ++ir)
                #pragma unroll
                for (int io = 0; io < 8; ++io)
                    acc[ir][io] = fmaf(af[ir], wf[io], acc[ir][io]);
        }
    }

    #pragma unroll
    for (int ir = 0; ir < 8; ++ir) {
        int r = p0 + ty*8 + ir;
        #pragma unroll
        for (int io4 = 0; io4 < 8; io4 += 4) {
            float4 v;
            v.x = acc[ir][io4+0]; v.y = acc[ir][io4+1];
            v.z = acc[ir][io4+2]; v.w = acc[ir][io4+3];
            *(float4*)(out + (size_t)r*NC + tx*8 + io4) = v;
        }
    }
}

// ---------------- launch (fork-join streams: knn ∥ setup+gemm3) ----------------
#define GEMM_SMEM  ((NC*SA + 16*NC) * 4)
#define G3_SMEM    (6*SLAB)
#define MAIN_SMEM  (6*SLAB + 512 + NC*3*4)

static cudaStream_t s_knn = 0, s_gem = 0;
static cudaEvent_t  e_fork = 0, e_knn = 0, e_gem = 0;

extern "C" void kernel_launch(void* const* d_in, const int* in_sizes, int n_in,
                              void* d_out, int out_size)
{
    const float* xyz   = (const float*)d_in[0];
    const float* feat  = (const float*)d_in[1];
    const float* Wq    = (const float*)d_in[2];
    const float* Wk    = (const float*)d_in[3];
    const float* Wv    = (const float*)d_in[4];
    const float* pW1   = (const float*)d_in[5];
    const float* pb1   = (const float*)d_in[6];
    const float* pg    = (const float*)d_in[7];
    const float* pbeta = (const float*)d_in[8];
    const float* pmean = (const float*)d_in[9];
    const float* pvar  = (const float*)d_in[10];
    const float* pW2   = (const float*)d_in[11];
    const float* pb2   = (const float*)d_in[12];
    const float* aW1   = (const float*)d_in[13];
    const float* ab1   = (const float*)d_in[14];
    const float* ag    = (const float*)d_in[15];
    const float* abeta = (const float*)d_in[16];
    const float* amean = (const float*)d_in[17];
    const float* avar  = (const float*)d_in[18];
    const float* aW2   = (const float*)d_in[19];
    const float* ab2   = (const float*)d_in[20];  (void)ab2;
    const float* Wout  = (const float*)d_in[21];
    float* out = (float*)d_out;

    void *p_t1, *p_t2, *p_vf, *p_outpre, *p_idx, *p_pd, *p_pi, *p_Woutt;
    cudaGetSymbolAddress(&p_t1, g_t1);
    cudaGetSymbolAddress(&p_t2, g_t2);
    cudaGetSymbolAddress(&p_vf, g_vf);
    cudaGetSymbolAddress(&p_outpre, g_outpre);
    cudaGetSymbolAddress(&p_idx, g_idx);
    cudaGetSymbolAddress(&p_pd, g_pd);
    cudaGetSymbolAddress(&p_pi, g_pi);
    cudaGetSymbolAddress(&p_Woutt, g_Woutt);

    cudaFuncSetAttribute(gemm_rt,    cudaFuncAttributeMaxDynamicSharedMemorySize, GEMM_SMEM);
    cudaFuncSetAttribute(gemm3_tc,   cudaFuncAttributeMaxDynamicSharedMemorySize, G3_SMEM);
    cudaFuncSetAttribute(fused_main, cudaFuncAttributeMaxDynamicSharedMemorySize, MAIN_SMEM);

    if (!s_knn) {
        cudaStreamCreateWithFlags(&s_knn, cudaStreamNonBlocking);
        cudaStreamCreateWithFlags(&s_gem, cudaStreamNonBlocking);
        cudaEventCreateWithFlags(&e_fork, cudaEventDisableTiming);
        cudaEventCreateWithFlags(&e_knn,  cudaEventDisableTiming);
        cudaEventCreateWithFlags(&e_gem,  cudaEventDisableTiming);
    }

    // fork
    cudaEventRecord(e_fork, 0);
    cudaStreamWaitEvent(s_knn, e_fork, 0);
    cudaStreamWaitEvent(s_gem, e_fork, 0);

    // branch A: KNN chain (xyz only)
    knn_part<<<dim3(NP/256, KSPLIT), 128, 0, s_knn>>>(xyz, (float*)p_pd, (int*)p_pi);
    knn_merge<<<NP/128, 128, 0, s_knn>>>((const float*)p_pd, (const int*)p_pi, (int*)p_idx);

    // branch B: weights + feature projections
    setup_kernel<<<NC, NC, 0, s_gem>>>(Wq, Wk, Wv, pW1, pb1, pg, pbeta, pmean, pvar,
                                       pW2, pb2, aW1, ab1, ag, abeta, amean, avar, aW2, Wout);
    gemm3_tc<<<NP/128, 512, G3_SMEM, s_gem>>>(feat, (float*)p_t1, (float*)p_t2, (float*)p_vf);

    // join
    cudaEventRecord(e_knn, s_knn);
    cudaEventRecord(e_gem, s_gem);
    cudaStreamWaitEvent(0, e_knn, 0);
    cudaStreamWaitEvent(0, e_gem, 0);

    fused_main<<<NP/8, 512, MAIN_SMEM>>>(xyz, pb2, (float*)p_outpre);

    gemm_rt<<<NP/128, 256, GEMM_SMEM>>>((const float*)p_outpre, (const float*)p_Woutt, out);
}